// round 3
// baseline (speedup 1.0000x reference)
#include <cuda_runtime.h>
#include <math.h>
#include <stdint.h>

// ---------------- problem dims ----------------
#define B_   8
#define S_   4096
#define D_   512
#define H_   1024
#define Kc_  4
#define CS_  64
#define NC_  64
#define BS_  (B_ * S_)      // 32768 tokens
#define R_   (B_ * CS_)     // 512 rows per chunk
#define ERR_CLIP  1.0f
#define GRAD_CLIP 1.0f
#define SCALE_    (2.0f / (float)CS_)   // 0.03125
#define SPLITK 4

// ---------------- device scratch (static: no runtime alloc) ----------------
__device__ float g_proj [(size_t)BS_ * D_];   // pre-conv projection scratch
__device__ float g_kc   [(size_t)BS_ * D_];   // chunk-major [NC][B][CS][D]
__device__ float g_vc   [(size_t)BS_ * D_];
__device__ float g_qc   [(size_t)BS_ * D_];
__device__ float g_ych  [(size_t)BS_ * D_];   // retrieval output, chunk-major
__device__ float g_yfl  [(size_t)BS_ * D_];   // flat [B,S,D]
__device__ float g_a1   [(size_t)R_ * H_];
__device__ float g_sd   [(size_t)R_ * H_];
__device__ float g_d1   [(size_t)R_ * H_];
__device__ float g_tb   [(size_t)R_ * H_];
__device__ float g_d2   [(size_t)R_ * D_];
__device__ float g_Wd1  [(size_t)H_ * D_];
__device__ float g_M1   [(size_t)H_ * D_];
__device__ float g_Wd2  [(size_t)D_ * H_];
__device__ float g_M2   [(size_t)D_ * H_];
__device__ float g_part [(size_t)SPLITK * R_ * H_];   // split-K partials (8MB)
__device__ float g_alpha[NC_];
__device__ float g_lrg  [NC_];
__device__ float g_eta  [NC_];

// ---------------- generic tiled fp32 GEMM with optional split-K ----------------
// MODE 0 (NT): C[M,N] = A[M,K] * B[N,K]^T
// MODE 1 (NN): C[M,N] = A[M,K] * B[K,N]
// MODE 2 (TN): C[M,N] = A[K,M]^T * B[K,N]
// BSUM: effective B element = B0[i] + B1[i]
// SPLIT>1: blockIdx.z = z computes K-slice [z*K/SPLIT, (z+1)*K/SPLIT) into C + z*M*N
#define TILE 64
#define BK   16

template <int MODE, bool BSUM, int SPLIT>
__global__ void __launch_bounds__(256)
gemm_kernel(const float* __restrict__ A, const float* __restrict__ B0,
            const float* __restrict__ B1, float* __restrict__ C,
            int M, int N, int K)
{
    __shared__ float As[BK][TILE + 4];
    __shared__ float Bs[BK][TILE + 4];
    const int tid = threadIdx.x;
    const int tx = tid & 15;          // 0..15 -> n frag (x4)
    const int ty = tid >> 4;          // 0..15 -> m frag (x4)
    const int m0 = blockIdx.y * TILE;
    const int n0 = blockIdx.x * TILE;
    const int z  = (SPLIT > 1) ? blockIdx.z : 0;
    const int kslice = K / SPLIT;
    const int kbeg = z * kslice;
    const int kend = kbeg + kslice;
    float* Cw = (SPLIT > 1) ? (C + (size_t)z * M * N) : C;

    float acc[4][4] = {};

    for (int k0 = kbeg; k0 < kend; k0 += BK) {
        // --- load A tile into As[k][m] ---
        if (MODE == 2) {
            const int kk = tid >> 4;
            const int mv = (tid & 15) << 2;
            const float4 a = *(const float4*)(A + (size_t)(k0 + kk) * M + m0 + mv);
            As[kk][mv + 0] = a.x; As[kk][mv + 1] = a.y;
            As[kk][mv + 2] = a.z; As[kk][mv + 3] = a.w;
        } else {
            const int mm = tid >> 2;
            const int kv = (tid & 3) << 2;
            const float4 a = *(const float4*)(A + (size_t)(m0 + mm) * K + k0 + kv);
            As[kv + 0][mm] = a.x; As[kv + 1][mm] = a.y;
            As[kv + 2][mm] = a.z; As[kv + 3][mm] = a.w;
        }
        // --- load B tile into Bs[k][n] ---
        if (MODE == 0) {
            const int nn = tid >> 2;
            const int kv = (tid & 3) << 2;
            const size_t off = (size_t)(n0 + nn) * K + k0 + kv;
            float4 b = *(const float4*)(B0 + off);
            if (BSUM) {
                const float4 c4 = *(const float4*)(B1 + off);
                b.x += c4.x; b.y += c4.y; b.z += c4.z; b.w += c4.w;
            }
            Bs[kv + 0][nn] = b.x; Bs[kv + 1][nn] = b.y;
            Bs[kv + 2][nn] = b.z; Bs[kv + 3][nn] = b.w;
        } else {
            const int kk = tid >> 4;
            const int nv = (tid & 15) << 2;
            const size_t off = (size_t)(k0 + kk) * N + n0 + nv;
            float4 b = *(const float4*)(B0 + off);
            if (BSUM) {
                const float4 c4 = *(const float4*)(B1 + off);
                b.x += c4.x; b.y += c4.y; b.z += c4.z; b.w += c4.w;
            }
            Bs[kk][nv + 0] = b.x; Bs[kk][nv + 1] = b.y;
            Bs[kk][nv + 2] = b.z; Bs[kk][nv + 3] = b.w;
        }
        __syncthreads();

#pragma unroll
        for (int kk = 0; kk < BK; kk++) {
            const float4 av = *(const float4*)&As[kk][ty << 2];
            const float4 bv = *(const float4*)&Bs[kk][tx << 2];
            acc[0][0] = fmaf(av.x, bv.x, acc[0][0]);
            acc[0][1] = fmaf(av.x, bv.y, acc[0][1]);
            acc[0][2] = fmaf(av.x, bv.z, acc[0][2]);
            acc[0][3] = fmaf(av.x, bv.w, acc[0][3]);
            acc[1][0] = fmaf(av.y, bv.x, acc[1][0]);
            acc[1][1] = fmaf(av.y, bv.y, acc[1][1]);
            acc[1][2] = fmaf(av.y, bv.z, acc[1][2]);
            acc[1][3] = fmaf(av.y, bv.w, acc[1][3]);
            acc[2][0] = fmaf(av.z, bv.x, acc[2][0]);
            acc[2][1] = fmaf(av.z, bv.y, acc[2][1]);
            acc[2][2] = fmaf(av.z, bv.z, acc[2][2]);
            acc[2][3] = fmaf(av.z, bv.w, acc[2][3]);
            acc[3][0] = fmaf(av.w, bv.x, acc[3][0]);
            acc[3][1] = fmaf(av.w, bv.y, acc[3][1]);
            acc[3][2] = fmaf(av.w, bv.z, acc[3][2]);
            acc[3][3] = fmaf(av.w, bv.w, acc[3][3]);
        }
        __syncthreads();
    }

#pragma unroll
    for (int i = 0; i < 4; i++) {
        const size_t m = (size_t)m0 + (ty << 2) + i;
        float4 o;
        o.x = acc[i][0]; o.y = acc[i][1]; o.z = acc[i][2]; o.w = acc[i][3];
        *(float4*)(Cw + m * N + n0 + (tx << 2)) = o;
    }
}

static void launch_gemm1(int mode, const float* A, const float* B0,
                         float* C, int M, int N, int K)
{
    dim3 grid(N / TILE, M / TILE), block(256);
    if (mode == 0) gemm_kernel<0, false, 1><<<grid, block>>>(A, B0, nullptr, C, M, N, K);
    else if (mode == 1) gemm_kernel<1, false, 1><<<grid, block>>>(A, B0, nullptr, C, M, N, K);
    else gemm_kernel<2, false, 1><<<grid, block>>>(A, B0, nullptr, C, M, N, K);
}

static void launch_gemm4(int mode, bool bsum, const float* A, const float* B0,
                         const float* B1, float* C, int M, int N, int K)
{
    dim3 grid(N / TILE, M / TILE, SPLITK), block(256);
    if (mode == 0) {
        if (bsum) gemm_kernel<0, true , SPLITK><<<grid, block>>>(A, B0, B1, C, M, N, K);
        else      gemm_kernel<0, false, SPLITK><<<grid, block>>>(A, B0, B1, C, M, N, K);
    } else if (mode == 1) {
        if (bsum) gemm_kernel<1, true , SPLITK><<<grid, block>>>(A, B0, B1, C, M, N, K);
        else      gemm_kernel<1, false, SPLITK><<<grid, block>>>(A, B0, B1, C, M, N, K);
    } else {
        if (bsum) gemm_kernel<2, true , SPLITK><<<grid, block>>>(A, B0, B1, C, M, N, K);
        else      gemm_kernel<2, false, SPLITK><<<grid, block>>>(A, B0, B1, C, M, N, K);
    }
}

// ---------------- fused split-K reduction epilogues ----------------
__device__ __forceinline__ float sigm(float x) { return 1.0f / (1.0f + __expf(-x)); }

__device__ __forceinline__ float4 sum4(const float4* __restrict__ p, int i, int n4)
{
    float4 a = p[i], b = p[i + n4], c = p[i + 2 * n4], d = p[i + 3 * n4];
    a.x += b.x + c.x + d.x;
    a.y += b.y + c.y + d.y;
    a.z += b.z + c.z + d.z;
    a.w += b.w + c.w + d.w;
    return a;
}

// a = silu(sum), sd = silu'(sum)
__global__ void epi_silu_kernel(const float4* __restrict__ p, float4* __restrict__ a,
                                float4* __restrict__ sd, int n4)
{
    const int i = blockIdx.x * blockDim.x + threadIdx.x;
    if (i >= n4) return;
    const float4 v = sum4(p, i, n4);
    float4 av, dv;
    {
        const float s = sigm(v.x); av.x = v.x * s; dv.x = s * (1.f + v.x * (1.f - s));
    }{
        const float s = sigm(v.y); av.y = v.y * s; dv.y = s * (1.f + v.y * (1.f - s));
    }{
        const float s = sigm(v.z); av.z = v.z * s; dv.z = s * (1.f + v.z * (1.f - s));
    }{
        const float s = sigm(v.w); av.w = v.w * s; dv.w = s * (1.f + v.w * (1.f - s));
    }
    a[i] = av; sd[i] = dv;
}

// out = silu(sum)
__global__ void epi_silu1_kernel(const float4* __restrict__ p, float4* __restrict__ o, int n4)
{
    const int i = blockIdx.x * blockDim.x + threadIdx.x;
    if (i >= n4) return;
    const float4 v = sum4(p, i, n4);
    float4 ov;
    ov.x = v.x * sigm(v.x); ov.y = v.y * sigm(v.y);
    ov.z = v.z * sigm(v.z); ov.w = v.w * sigm(v.w);
    o[i] = ov;
}

// d2 = SCALE * clip(sum - v, +-ERR_CLIP)
__global__ void epi_d2_kernel(const float4* __restrict__ p, const float4* __restrict__ v,
                              float4* __restrict__ o, int n4)
{
    const int i = blockIdx.x * blockDim.x + threadIdx.x;
    if (i >= n4) return;
    const float4 s = sum4(p, i, n4);
    const float4 vv = v[i];
    float4 ov;
    ov.x = SCALE_ * fminf(fmaxf(s.x - vv.x, -ERR_CLIP), ERR_CLIP);
    ov.y = SCALE_ * fminf(fmaxf(s.y - vv.y, -ERR_CLIP), ERR_CLIP);
    ov.z = SCALE_ * fminf(fmaxf(s.z - vv.z, -ERR_CLIP), ERR_CLIP);
    ov.w = SCALE_ * fminf(fmaxf(s.w - vv.w, -ERR_CLIP), ERR_CLIP);
    o[i] = ov;
}

// o = sum * b (d1 = backprop * silu')
__global__ void epi_mul_kernel(const float4* __restrict__ p, const float4* __restrict__ b,
                               float4* __restrict__ o, int n4)
{
    const int i = blockIdx.x * blockDim.x + threadIdx.x;
    if (i >= n4) return;
    const float4 s = sum4(p, i, n4);
    const float4 bv = b[i];
    float4 ov;
    ov.x = s.x * bv.x; ov.y = s.y * bv.y; ov.z = s.z * bv.z; ov.w = s.w * bv.w;
    o[i] = ov;
}

// gc = clip(sum); M = eta*M - lr*gc; Wd = (1-a)*Wd + M
__global__ void epi_update_kernel(const float4* __restrict__ p, float4* __restrict__ Mo,
                                  float4* __restrict__ Wd, int c, int n4)
{
    const int i = blockIdx.x * blockDim.x + threadIdx.x;
    if (i >= n4) return;
    const float a = g_alpha[c], l = g_lrg[c], e = g_eta[c];
    const float4 g = sum4(p, i, n4);
    float4 m = Mo[i], w = Wd[i];
    m.x = e * m.x - l * fminf(fmaxf(g.x, -GRAD_CLIP), GRAD_CLIP);
    m.y = e * m.y - l * fminf(fmaxf(g.y, -GRAD_CLIP), GRAD_CLIP);
    m.z = e * m.z - l * fminf(fmaxf(g.z, -GRAD_CLIP), GRAD_CLIP);
    m.w = e * m.w - l * fminf(fmaxf(g.w, -GRAD_CLIP), GRAD_CLIP);
    w.x = (1.f - a) * w.x + m.x;
    w.y = (1.f - a) * w.y + m.y;
    w.z = (1.f - a) * w.z + m.z;
    w.w = (1.f - a) * w.w + m.w;
    Mo[i] = m; Wd[i] = w;
}

// o = sum (retrieval write)
__global__ void epi_copy_kernel(const float4* __restrict__ p, float4* __restrict__ o, int n4)
{
    const int i = blockIdx.x * blockDim.x + threadIdx.x;
    if (i >= n4) return;
    o[i] = sum4(p, i, n4);
}

// ---------------- misc kernels ----------------
__global__ void zero_state_kernel()
{
    const size_t i = (size_t)blockIdx.x * blockDim.x + threadIdx.x;
    if (i < (size_t)H_ * D_) {
        g_Wd1[i] = 0.f; g_M1[i] = 0.f; g_Wd2[i] = 0.f; g_M2[i] = 0.f;
    }
}

// causal depthwise conv (left pad K-1), writes chunk-major [NC][B][CS][D]
__global__ void conv_chunk_kernel(const float* __restrict__ in, const float* __restrict__ w,
                                  const float* __restrict__ bias, float* __restrict__ out)
{
    const size_t i = (size_t)blockIdx.x * blockDim.x + threadIdx.x;
    if (i >= (size_t)BS_ * D_) return;
    const int d = (int)(i & (D_ - 1));
    const size_t bs = i >> 9;            // b*S + s
    const int s = (int)(bs & (S_ - 1));
    const int b = (int)(bs >> 12);
    float acc = bias[d];
#pragma unroll
    for (int j = 0; j < Kc_; j++) {
        const int sp = s - (Kc_ - 1) + j;
        if (sp >= 0)
            acc = fmaf(w[d * Kc_ + j], in[((size_t)b * S_ + sp) * D_ + d], acc);
    }
    const int c  = s >> 6;
    const int cs = s & 63;
    out[((((size_t)c * B_ + b) * CS_ + cs) << 9) + d] = acc;
}

// per-chunk scalar gates: sigmoid(x.w + b) mean-pooled over (B, CS)
__global__ void gates_kernel(const float* __restrict__ x,
                             const float* __restrict__ wd, const float* __restrict__ bd,
                             const float* __restrict__ wl, const float* __restrict__ bl,
                             const float* __restrict__ we, const float* __restrict__ be)
{
    const int c = blockIdx.x;
    const int t = threadIdx.x;          // 0..511
    const int b  = t >> 6;
    const int cs = t & 63;
    const float4* xr = (const float4*)(x + (((size_t)b * S_ + (size_t)c * CS_ + cs) << 9));
    const float4* w0 = (const float4*)wd;
    const float4* w1 = (const float4*)wl;
    const float4* w2 = (const float4*)we;
    float s0 = 0.f, s1 = 0.f, s2 = 0.f;
#pragma unroll 4
    for (int d = 0; d < D_ / 4; d++) {
        const float4 xv = xr[d];
        const float4 a0 = w0[d], a1 = w1[d], a2 = w2[d];
        s0 += xv.x * a0.x + xv.y * a0.y + xv.z * a0.z + xv.w * a0.w;
        s1 += xv.x * a1.x + xv.y * a1.y + xv.z * a1.z + xv.w * a1.w;
        s2 += xv.x * a2.x + xv.y * a2.y + xv.z * a2.z + xv.w * a2.w;
    }
    s0 = sigm(s0 + bd[0]);
    s1 = sigm(s1 + bl[0]);
    s2 = sigm(s2 + be[0]);

    __shared__ float r0[512], r1[512], r2[512];
    r0[t] = s0; r1[t] = s1; r2[t] = s2;
    __syncthreads();
    for (int off = 256; off > 0; off >>= 1) {
        if (t < off) { r0[t] += r0[t + off]; r1[t] += r1[t + off]; r2[t] += r2[t + off]; }
        __syncthreads();
    }
    if (t == 0) {
        g_alpha[c] = r0[0] * (1.0f / 512.0f);
        g_lrg[c]   = r1[0] * (1.0f / 512.0f);
        g_eta[c]   = r2[0] * (1.0f / 512.0f);
    }
}

// chunk-major -> flat [B,S,D]
__global__ void permute_y_kernel()
{
    const size_t i = (size_t)blockIdx.x * blockDim.x + threadIdx.x;
    if (i >= (size_t)BS_ * D_) return;
    const int d = (int)(i & (D_ - 1));
    const size_t r = i >> 9;
    const int s = (int)(r & (S_ - 1));
    const int b = (int)(r >> 12);
    const int c  = s >> 6;
    const int cs = s & 63;
    g_yfl[i] = g_ych[((((size_t)c * B_ + b) * CS_ + cs) << 9) + d];
}

// ---------------- entry point ----------------
extern "C" void kernel_launch(void* const* d_in, const int* in_sizes, int n_in,
                              void* d_out, int out_size)
{
    (void)in_sizes; (void)n_in; (void)out_size;
    const float* x    = (const float*)d_in[0];
    const float* Wk   = (const float*)d_in[1];
    const float* Wv   = (const float*)d_in[2];
    const float* Wq   = (const float*)d_in[3];
    const float* Wout = (const float*)d_in[4];
    const float* ckw  = (const float*)d_in[5];
    const float* ckb  = (const float*)d_in[6];
    const float* cvw  = (const float*)d_in[7];
    const float* cvb  = (const float*)d_in[8];
    const float* cqw  = (const float*)d_in[9];
    const float* cqb  = (const float*)d_in[10];
    const float* wdec = (const float*)d_in[11];
    const float* bdec = (const float*)d_in[12];
    const float* wlr  = (const float*)d_in[13];
    const float* blr  = (const float*)d_in[14];
    const float* weta = (const float*)d_in[15];
    const float* beta = (const float*)d_in[16];
    const float* W1   = (const float*)d_in[17];
    const float* W2   = (const float*)d_in[18];
    float* out = (float*)d_out;

    float *proj, *kc, *vc, *qc, *ych, *yfl, *a1, *sd, *d1, *tb, *d2, *part;
    float *Wd1, *M1, *Wd2, *M2;
    cudaGetSymbolAddress((void**)&proj, g_proj);
    cudaGetSymbolAddress((void**)&kc,   g_kc);
    cudaGetSymbolAddress((void**)&vc,   g_vc);
    cudaGetSymbolAddress((void**)&qc,   g_qc);
    cudaGetSymbolAddress((void**)&ych,  g_ych);
    cudaGetSymbolAddress((void**)&yfl,  g_yfl);
    cudaGetSymbolAddress((void**)&a1,   g_a1);
    cudaGetSymbolAddress((void**)&sd,   g_sd);
    cudaGetSymbolAddress((void**)&d1,   g_d1);
    cudaGetSymbolAddress((void**)&tb,   g_tb);
    cudaGetSymbolAddress((void**)&d2,   g_d2);
    cudaGetSymbolAddress((void**)&part, g_part);
    cudaGetSymbolAddress((void**)&Wd1,  g_Wd1);
    cudaGetSymbolAddress((void**)&M1,   g_M1);
    cudaGetSymbolAddress((void**)&Wd2,  g_Wd2);
    cudaGetSymbolAddress((void**)&M2,   g_M2);

    const int nRH = R_ * H_;      // 524288
    const int nRD = R_ * D_;      // 262144
    const int nHD = H_ * D_;      // 524288
    const int nRH4 = nRH / 4, nRD4 = nRD / 4, nHD4 = nHD / 4;
    const int EB = 256;

    zero_state_kernel<<<(nHD + 255) / 256, 256>>>();
    gates_kernel<<<NC_, 512>>>(x, wdec, bdec, wlr, blr, weta, beta);

    // projections + causal depthwise conv -> chunk-major k,v,q
    const int nTOT = BS_ * D_;
    launch_gemm1(0, x, Wk, proj, BS_, D_, D_);
    conv_chunk_kernel<<<(nTOT + 255) / 256, 256>>>(proj, ckw, ckb, kc);
    launch_gemm1(0, x, Wv, proj, BS_, D_, D_);
    conv_chunk_kernel<<<(nTOT + 255) / 256, 256>>>(proj, cvw, cvb, vc);
    launch_gemm1(0, x, Wq, proj, BS_, D_, D_);
    conv_chunk_kernel<<<(nTOT + 255) / 256, 256>>>(proj, cqw, cqb, qc);

    const float4* part4 = (const float4*)part;

    // sequential chunk scan
    for (int c = 0; c < NC_; c++) {
        const float* kcc = kc + (size_t)c * nRD;
        const float* vcc = vc + (size_t)c * nRD;
        const float* qcc = qc + (size_t)c * nRD;

        // h1 = Kc @ (W1+Wd1)^T ; a1 = silu, sd = silu'
        launch_gemm4(0, true, kcc, W1, Wd1, part, R_, H_, D_);
        epi_silu_kernel<<<(nRH4 + EB - 1) / EB, EB>>>(part4, (float4*)a1, (float4*)sd, nRH4);
        // pred = a1 @ (W2+Wd2)^T ; d2 = scale*clip(pred - v)
        launch_gemm4(0, true, a1, W2, Wd2, part, R_, D_, H_);
        epi_d2_kernel<<<(nRD4 + EB - 1) / EB, EB>>>(part4, (const float4*)vcc, (float4*)d2, nRD4);
        // d1 = (d2 @ E2) * sd   (uses OLD Wd2 -> precedes updates)
        launch_gemm4(1, true, d2, W2, Wd2, part, R_, H_, D_);
        epi_mul_kernel<<<(nRH4 + EB - 1) / EB, EB>>>(part4, (const float4*)sd, (float4*)d1, nRH4);
        // g2 = clip(d2^T @ a1) -> momentum+decay update of (M2, Wd2)
        launch_gemm4(2, false, d2, a1, nullptr, part, D_, H_, R_);
        epi_update_kernel<<<(nHD4 + EB - 1) / EB, EB>>>(part4, (float4*)M2, (float4*)Wd2, c, nHD4);
        // g1 = clip(d1^T @ Kc) -> update (M1, Wd1)
        launch_gemm4(2, false, d1, kcc, nullptr, part, H_, D_, R_);
        epi_update_kernel<<<(nHD4 + EB - 1) / EB, EB>>>(part4, (float4*)M1, (float4*)Wd1, c, nHD4);
        // retrieval with updated weights
        launch_gemm4(0, true, qcc, W1, Wd1, part, R_, H_, D_);
        epi_silu1_kernel<<<(nRH4 + EB - 1) / EB, EB>>>(part4, (float4*)tb, nRH4);
        launch_gemm4(0, true, tb, W2, Wd2, part, R_, D_, H_);
        epi_copy_kernel<<<(nRD4 + EB - 1) / EB, EB>>>(part4, (float4*)(ych + (size_t)c * nRD), nRD4);
    }

    permute_y_kernel<<<(nTOT + 255) / 256, 256>>>();
    launch_gemm1(0, yfl, Wout, out, BS_, D_, D_);
}

// round 5
// speedup vs baseline: 1.0484x; 1.0484x over previous
#include <cuda_runtime.h>
#include <cuda_bf16.h>
#include <math.h>
#include <stdint.h>

// ---------------- problem dims ----------------
#define B_   8
#define S_   4096
#define D_   512
#define H_   1024
#define Kc_  4
#define CS_  64
#define NC_  64
#define BS_  (B_ * S_)      // 32768 tokens
#define R_   512            // rows per chunk (B*CS)
#define ERR_CLIP  1.0f
#define GRAD_CLIP 1.0f
#define SCALE_    0.03125f  // 2/CS

// ---------------- device scratch ----------------
__device__ float g_proj[(size_t)BS_ * D_];
__device__ float g_kc  [(size_t)BS_ * D_];   // [NC][R][D]
__device__ float g_vc  [(size_t)BS_ * D_];
__device__ float g_qc  [(size_t)BS_ * D_];
__device__ float g_ych [(size_t)BS_ * D_];
__device__ float g_yfl [(size_t)BS_ * D_];
__device__ float g_a1  [(size_t)R_ * H_];
__device__ float g_sd  [(size_t)R_ * H_];
__device__ float g_d1  [(size_t)R_ * H_];
__device__ float g_tb  [(size_t)R_ * H_];
__device__ float g_d2  [(size_t)R_ * D_];
__device__ float g_Wd1 [(size_t)H_ * D_];
__device__ float g_M1  [(size_t)H_ * D_];
__device__ float g_Wd2 [(size_t)D_ * H_];
__device__ float g_M2  [(size_t)D_ * H_];
__device__ float g_alpha[NC_];
__device__ float g_lrg [NC_];
__device__ float g_eta [NC_];

// ---------------- helpers ----------------
__device__ __forceinline__ float sigm(float x) { return 1.0f / (1.0f + __expf(-x)); }

__device__ __forceinline__ uint32_t smem_u32(const void* p) {
    uint32_t a;
    asm("{ .reg .u64 t; cvta.to.shared.u64 t, %1; cvt.u32.u64 %0, t; }" : "=r"(a) : "l"(p));
    return a;
}

__device__ __forceinline__ void ldsm4(uint32_t* r, uint32_t a) {
    asm volatile("ldmatrix.sync.aligned.m8n8.x4.shared.b16 {%0,%1,%2,%3}, [%4];"
        : "=r"(r[0]), "=r"(r[1]), "=r"(r[2]), "=r"(r[3]) : "r"(a));
}
__device__ __forceinline__ void ldsm4t(uint32_t* r, uint32_t a) {
    asm volatile("ldmatrix.sync.aligned.m8n8.x4.trans.shared.b16 {%0,%1,%2,%3}, [%4];"
        : "=r"(r[0]), "=r"(r[1]), "=r"(r[2]), "=r"(r[3]) : "r"(a));
}
__device__ __forceinline__ void mma16816(float* c, const uint32_t* a, uint32_t b0, uint32_t b1) {
    asm volatile("mma.sync.aligned.m16n8k16.row.col.f32.bf16.bf16.f32 "
        "{%0,%1,%2,%3}, {%4,%5,%6,%7}, {%8,%9}, {%0,%1,%2,%3};"
        : "+f"(c[0]), "+f"(c[1]), "+f"(c[2]), "+f"(c[3])
        : "r"(a[0]), "r"(a[1]), "r"(a[2]), "r"(a[3]), "r"(b0), "r"(b1));
}

__device__ __forceinline__ uint32_t b2u(__nv_bfloat162 v) {
    union { __nv_bfloat162 b; uint32_t u; } x; x.b = v; return x.u;
}

// split 8 fp32 -> 8 hi-bf16 + 8 lo-bf16 (residual)
__device__ __forceinline__ void split8(float4 u, float4 v, uint4& hi, uint4& lo)
{
    __nv_bfloat162 h0(__float2bfloat16_rn(u.x), __float2bfloat16_rn(u.y));
    __nv_bfloat162 h1(__float2bfloat16_rn(u.z), __float2bfloat16_rn(u.w));
    __nv_bfloat162 h2(__float2bfloat16_rn(v.x), __float2bfloat16_rn(v.y));
    __nv_bfloat162 h3(__float2bfloat16_rn(v.z), __float2bfloat16_rn(v.w));
    hi = make_uint4(b2u(h0), b2u(h1), b2u(h2), b2u(h3));
    __nv_bfloat162 l0(__float2bfloat16_rn(u.x - __bfloat162float(h0.x)),
                      __float2bfloat16_rn(u.y - __bfloat162float(h0.y)));
    __nv_bfloat162 l1(__float2bfloat16_rn(u.z - __bfloat162float(h1.x)),
                      __float2bfloat16_rn(u.w - __bfloat162float(h1.y)));
    __nv_bfloat162 l2(__float2bfloat16_rn(v.x - __bfloat162float(h2.x)),
                      __float2bfloat16_rn(v.y - __bfloat162float(h2.y)));
    __nv_bfloat162 l3(__float2bfloat16_rn(v.z - __bfloat162float(h3.x)),
                      __float2bfloat16_rn(v.w - __bfloat162float(h3.y)));
    lo = make_uint4(b2u(l0), b2u(l1), b2u(l2), b2u(l3));
}

// ---------------- staged loads: 64x32 fp32 tile per operand per chunk ----------------
// direct (TR=false): source rows = output dim (m or n), K-contiguous; thread t: row=t>>1, khalf=t&1
// trans  (TR=true):  source rows = k, dim-contiguous;                thread t: row=t>>2, quarter=t&3
template <bool AT, bool BT, bool BSUM>
__device__ __forceinline__ void load_stage(float4* sa, float4* sb,
    const float* __restrict__ A, const float* __restrict__ B0, const float* __restrict__ B1,
    int M, int N, int K, int m0, int n0, int k0, int t)
{
    const float* pa = AT ? (A + (size_t)(k0 + (t >> 2)) * M + m0 + ((t & 3) << 4))
                         : (A + (size_t)(m0 + (t >> 1)) * K + k0 + ((t & 1) << 4));
#pragma unroll
    for (int i = 0; i < 4; i++) sa[i] = ((const float4*)pa)[i];
    const float* pb = BT ? (B0 + (size_t)(k0 + (t >> 2)) * N + n0 + ((t & 3) << 4))
                         : (B0 + (size_t)(n0 + (t >> 1)) * K + k0 + ((t & 1) << 4));
#pragma unroll
    for (int i = 0; i < 4; i++) sb[i] = ((const float4*)pb)[i];
    if (BSUM) {
        const float* pc = BT ? (B1 + (size_t)(k0 + (t >> 2)) * N + n0 + ((t & 3) << 4))
                             : (B1 + (size_t)(n0 + (t >> 1)) * K + k0 + ((t & 1) << 4));
#pragma unroll
        for (int i = 0; i < 4; i++) {
            const float4 v = ((const float4*)pc)[i];
            sb[i].x += v.x; sb[i].y += v.y; sb[i].z += v.z; sb[i].w += v.w;
        }
    }
}

// store 16 staged fp32 into hi/lo bf16 tiles with XOR swizzle
// direct tile: 64 rows x 4 chunks(16B), pitch 64;  swz: c ^ ((row>>1)&3)
// trans tile:  32 rows x 8 chunks(16B), pitch 128; swz: c ^ (row&7)
template <bool TR>
__device__ __forceinline__ void store_tile(char* Hd, char* Ld, const float4* s, int t)
{
    int row, cb;
    if (!TR) { row = t >> 1; cb = (t & 1) << 1; }
    else     { row = t >> 2; cb = (t & 3) << 1; }
    const int pitch = TR ? 128 : 64;
    const int c0 = TR ? (cb ^ (row & 7)) : (cb ^ ((row >> 1) & 3));
    const int c1 = TR ? ((cb + 1) ^ (row & 7)) : ((cb + 1) ^ ((row >> 1) & 3));
    uint4 h0, l0, h1, l1;
    split8(s[0], s[1], h0, l0);
    split8(s[2], s[3], h1, l1);
    *(uint4*)(Hd + row * pitch + (c0 << 4)) = h0;
    *(uint4*)(Hd + row * pitch + (c1 << 4)) = h1;
    *(uint4*)(Ld + row * pitch + (c0 << 4)) = l0;
    *(uint4*)(Ld + row * pitch + (c1 << 4)) = l1;
}

// ---------------- one K=32 chunk of MMAs (3 emulation passes) ----------------
template <bool AT, bool BT>
__device__ __forceinline__ void mma_chunk(uint32_t base, float acc[2][4][4],
                                          int wm, int wn, int lane)
{
#pragma unroll
    for (int koi = 0; koi < 2; koi++) {
        const int ko = koi << 4;
        uint32_t ah[2][4], al[2][4], bh[2][4], bl[2][4];
#pragma unroll
        for (int i = 0; i < 2; i++) {
            const int mf = wm * 32 + i * 16;
            if (!AT) {
                const int row = mf + (lane & 7) + ((lane & 8) ? 8 : 0);
                const int ck = (ko >> 3) + ((lane >> 4) & 1);
                const uint32_t off = row * 64 + ((ck ^ ((row >> 1) & 3)) << 4);
                ldsm4(ah[i], base + off);
                ldsm4(al[i], base + 4096 + off);
            } else {
                const int row = ko + (lane & 7) + ((lane & 16) ? 8 : 0);
                const int ck = (mf >> 3) + ((lane >> 3) & 1);
                const uint32_t off = row * 128 + ((ck ^ (row & 7)) << 4);
                ldsm4t(ah[i], base + off);
                ldsm4t(al[i], base + 4096 + off);
            }
        }
#pragma unroll
        for (int jp = 0; jp < 2; jp++) {
            const int nf = wn * 32 + jp * 16;
            if (!BT) {
                const int row = nf + (lane & 7) + ((lane & 16) ? 8 : 0);
                const int ck = (ko >> 3) + ((lane >> 3) & 1);
                const uint32_t off = row * 64 + ((ck ^ ((row >> 1) & 3)) << 4);
                ldsm4(bh[jp], base + 8192 + off);
                ldsm4(bl[jp], base + 12288 + off);
            } else {
                const int row = ko + (lane & 7) + ((lane & 8) ? 8 : 0);
                const int ck = (nf >> 3) + ((lane >> 4) & 1);
                const uint32_t off = row * 128 + ((ck ^ (row & 7)) << 4);
                ldsm4t(bh[jp], base + 8192 + off);
                ldsm4t(bl[jp], base + 12288 + off);
            }
        }
#pragma unroll
        for (int i = 0; i < 2; i++)
#pragma unroll
            for (int j = 0; j < 4; j++) {
                const int jp = j >> 1, wv = (j & 1) << 1;
                mma16816(acc[i][j], ah[i], bh[jp][wv], bh[jp][wv + 1]);  // hi*hi
                mma16816(acc[i][j], ah[i], bl[jp][wv], bl[jp][wv + 1]);  // hi*lo
                mma16816(acc[i][j], al[i], bh[jp][wv], bh[jp][wv + 1]);  // lo*hi
            }
    }
}

// ---------------- tensor GEMM: C[M,N] = opA(A) * opB(B)^eff with fused epilogue --------
// AT=0: A is [M,K] ; AT=1: A is [K,M]
// BT=0: B is [N,K] ; BT=1: B is [K,N]      (math: C[m,n] = sum_k a[m,k] b[n,k]-equiv)
// BSUM: B-element = B0 + B1
// EPI 0: C = acc
// EPI 1: C = silu(acc), U1 = silu'(acc)
// EPI 2: C = SCALE*clip(acc - X1, +-ERR_CLIP)
// EPI 3: C = acc * X1
// EPI 4: g = clip(acc); U1 = eta*U1 - lr*g; U2 = (1-alpha)*U2 + U1   (gate index 'gate')
// EPI 5: C = silu(acc)
template <int EPI, bool AT, bool BT, bool BSUM>
__global__ void __launch_bounds__(128)
mma_gemm(const float* __restrict__ A, const float* __restrict__ B0,
         const float* __restrict__ B1, float* __restrict__ C,
         const float* __restrict__ X1, float* __restrict__ U1, float* __restrict__ U2,
         int M, int N, int K, int gate)
{
    __shared__ __align__(1024) char smtiles[4][4096];   // AH, AL, BH, BL
    const int t = threadIdx.x, lane = t & 31, w = t >> 5;
    const int wm = w & 1, wn = w >> 1;
    const int m0 = blockIdx.y << 6, n0 = blockIdx.x << 6;
    const uint32_t base = smem_u32(smtiles);

    float acc[2][4][4] = {};
    float4 sa[4], sb[4];
    load_stage<AT, BT, BSUM>(sa, sb, A, B0, B1, M, N, K, m0, n0, 0, t);

    const int nch = K >> 5;
    for (int ch = 0; ch < nch; ch++) {
        store_tile<AT>((char*)smtiles[0], (char*)smtiles[1], sa, t);
        store_tile<BT>((char*)smtiles[2], (char*)smtiles[3], sb, t);
        __syncthreads();
        if (ch + 1 < nch)
            load_stage<AT, BT, BSUM>(sa, sb, A, B0, B1, M, N, K, m0, n0, (ch + 1) << 5, t);
        mma_chunk<AT, BT>(base, acc, wm, wn, lane);
        __syncthreads();
    }

    // ---- epilogue ----
    const float ga = (EPI == 4) ? g_alpha[gate] : 0.f;
    const float gl = (EPI == 4) ? g_lrg[gate] : 0.f;
    const float ge = (EPI == 4) ? g_eta[gate] : 0.f;
#pragma unroll
    for (int i = 0; i < 2; i++)
#pragma unroll
        for (int j = 0; j < 4; j++) {
            const float* a = acc[i][j];
            const int mr0 = m0 + wm * 32 + i * 16 + (lane >> 2);
            const int nc  = n0 + wn * 32 + j * 8 + ((lane & 3) << 1);
            const size_t i0 = (size_t)mr0 * N + nc;
            const size_t i1 = (size_t)(mr0 + 8) * N + nc;

            if (EPI == 0) {
                *(float2*)(C + i0) = make_float2(a[0], a[1]);
                *(float2*)(C + i1) = make_float2(a[2], a[3]);
            } else if (EPI == 1) {
                float s0 = sigm(a[0]), s1 = sigm(a[1]), s2 = sigm(a[2]), s3 = sigm(a[3]);
                *(float2*)(C + i0) = make_float2(a[0] * s0, a[1] * s1);
                *(float2*)(C + i1) = make_float2(a[2] * s2, a[3] * s3);
                *(float2*)(U1 + i0) = make_float2(s0 * (1.f + a[0] * (1.f - s0)),
                                                  s1 * (1.f + a[1] * (1.f - s1)));
                *(float2*)(U1 + i1) = make_float2(s2 * (1.f + a[2] * (1.f - s2)),
                                                  s3 * (1.f + a[3] * (1.f - s3)));
            } else if (EPI == 2) {
                const float2 v0 = *(const float2*)(X1 + i0);
                const float2 v1 = *(const float2*)(X1 + i1);
                *(float2*)(C + i0) = make_float2(
                    SCALE_ * fminf(fmaxf(a[0] - v0.x, -ERR_CLIP), ERR_CLIP),
                    SCALE_ * fminf(fmaxf(a[1] - v0.y, -ERR_CLIP), ERR_CLIP));
                *(float2*)(C + i1) = make_float2(
                    SCALE_ * fminf(fmaxf(a[2] - v1.x, -ERR_CLIP), ERR_CLIP),
                    SCALE_ * fminf(fmaxf(a[3] - v1.y, -ERR_CLIP), ERR_CLIP));
            } else if (EPI == 3) {
                const float2 v0 = *(const float2*)(X1 + i0);
                const float2 v1 = *(const float2*)(X1 + i1);
                *(float2*)(C + i0) = make_float2(a[0] * v0.x, a[1] * v0.y);
                *(float2*)(C + i1) = make_float2(a[2] * v1.x, a[3] * v1.y);
            } else if (EPI == 4) {
                float2 mo0 = *(float2*)(U1 + i0), mo1 = *(float2*)(U1 + i1);
                float2 wd0 = *(float2*)(U2 + i0), wd1 = *(float2*)(U2 + i1);
                mo0.x = ge * mo0.x - gl * fminf(fmaxf(a[0], -GRAD_CLIP), GRAD_CLIP);
                mo0.y = ge * mo0.y - gl * fminf(fmaxf(a[1], -GRAD_CLIP), GRAD_CLIP);
                mo1.x = ge * mo1.x - gl * fminf(fmaxf(a[2], -GRAD_CLIP), GRAD_CLIP);
                mo1.y = ge * mo1.y - gl * fminf(fmaxf(a[3], -GRAD_CLIP), GRAD_CLIP);
                wd0.x = (1.f - ga) * wd0.x + mo0.x;
                wd0.y = (1.f - ga) * wd0.y + mo0.y;
                wd1.x = (1.f - ga) * wd1.x + mo1.x;
                wd1.y = (1.f - ga) * wd1.y + mo1.y;
                *(float2*)(U1 + i0) = mo0; *(float2*)(U1 + i1) = mo1;
                *(float2*)(U2 + i0) = wd0; *(float2*)(U2 + i1) = wd1;
            } else { // EPI 5
                *(float2*)(C + i0) = make_float2(a[0] * sigm(a[0]), a[1] * sigm(a[1]));
                *(float2*)(C + i1) = make_float2(a[2] * sigm(a[2]), a[3] * sigm(a[3]));
            }
        }
}

template <int EPI, bool AT, bool BT, bool BSUM>
static void run(const float* A, const float* B0, const float* B1, float* C,
                const float* X1, float* U1, float* U2, int M, int N, int K, int gate)
{
    dim3 grid(N >> 6, M >> 6);
    mma_gemm<EPI, AT, BT, BSUM><<<grid, 128>>>(A, B0, B1, C, X1, U1, U2, M, N, K, gate);
}

// ---------------- misc kernels ----------------
__global__ void zero_state_kernel()
{
    const size_t i = (size_t)blockIdx.x * blockDim.x + threadIdx.x;
    if (i < (size_t)H_ * D_) {
        g_Wd1[i] = 0.f; g_M1[i] = 0.f; g_Wd2[i] = 0.f; g_M2[i] = 0.f;
    }
}

// causal depthwise conv (left pad K-1), writes chunk-major [NC][R][D]
__global__ void conv_chunk_kernel(const float* __restrict__ in, const float* __restrict__ w,
                                  const float* __restrict__ bias, float* __restrict__ out)
{
    const size_t i = (size_t)blockIdx.x * blockDim.x + threadIdx.x;
    if (i >= (size_t)BS_ * D_) return;
    const int d = (int)(i & (D_ - 1));
    const size_t bs = i >> 9;
    const int s = (int)(bs & (S_ - 1));
    const int b = (int)(bs >> 12);
    float acc = bias[d];
#pragma unroll
    for (int j = 0; j < Kc_; j++) {
        const int sp = s - (Kc_ - 1) + j;
        if (sp >= 0)
            acc = fmaf(w[d * Kc_ + j], in[((size_t)b * S_ + sp) * D_ + d], acc);
    }
    const int c  = s >> 6;
    const int cs = s & 63;
    out[(((size_t)c * R_ + (b * CS_ + cs)) << 9) + d] = acc;
}

__global__ void gates_kernel(const float* __restrict__ x,
                             const float* __restrict__ wd, const float* __restrict__ bd,
                             const float* __restrict__ wl, const float* __restrict__ bl,
                             const float* __restrict__ we, const float* __restrict__ be)
{
    const int c = blockIdx.x;
    const int t = threadIdx.x;          // 0..511
    const int b  = t >> 6;
    const int cs = t & 63;
    const float4* xr = (const float4*)(x + (((size_t)b * S_ + (size_t)c * CS_ + cs) << 9));
    const float4* w0 = (const float4*)wd;
    const float4* w1 = (const float4*)wl;
    const float4* w2 = (const float4*)we;
    float s0 = 0.f, s1 = 0.f, s2 = 0.f;
#pragma unroll 4
    for (int d = 0; d < D_ / 4; d++) {
        const float4 xv = xr[d];
        const float4 a0 = w0[d], a1 = w1[d], a2 = w2[d];
        s0 += xv.x * a0.x + xv.y * a0.y + xv.z * a0.z + xv.w * a0.w;
        s1 += xv.x * a1.x + xv.y * a1.y + xv.z * a1.z + xv.w * a1.w;
        s2 += xv.x * a2.x + xv.y * a2.y + xv.z * a2.z + xv.w * a2.w;
    }
    s0 = sigm(s0 + bd[0]);
    s1 = sigm(s1 + bl[0]);
    s2 = sigm(s2 + be[0]);

    __shared__ float r0[512], r1[512], r2[512];
    r0[t] = s0; r1[t] = s1; r2[t] = s2;
    __syncthreads();
    for (int off = 256; off > 0; off >>= 1) {
        if (t < off) { r0[t] += r0[t + off]; r1[t] += r1[t + off]; r2[t] += r2[t + off]; }
        __syncthreads();
    }
    if (t == 0) {
        g_alpha[c] = r0[0] * (1.0f / 512.0f);
        g_lrg[c]   = r1[0] * (1.0f / 512.0f);
        g_eta[c]   = r2[0] * (1.0f / 512.0f);
    }
}

__global__ void permute_y_kernel()
{
    const size_t i = (size_t)blockIdx.x * blockDim.x + threadIdx.x;
    if (i >= (size_t)BS_ * D_) return;
    const int d = (int)(i & (D_ - 1));
    const size_t rw = i >> 9;
    const int s = (int)(rw & (S_ - 1));
    const int b = (int)(rw >> 12);
    const int c  = s >> 6;
    const int cs = s & 63;
    g_yfl[i] = g_ych[(((size_t)c * R_ + (b * CS_ + cs)) << 9) + d];
}

// ---------------- entry point ----------------
extern "C" void kernel_launch(void* const* d_in, const int* in_sizes, int n_in,
                              void* d_out, int out_size)
{
    (void)in_sizes; (void)n_in; (void)out_size;
    const float* x    = (const float*)d_in[0];
    const float* Wk   = (const float*)d_in[1];
    const float* Wv   = (const float*)d_in[2];
    const float* Wq   = (const float*)d_in[3];
    const float* Wout = (const float*)d_in[4];
    const float* ckw  = (const float*)d_in[5];
    const float* ckb  = (const float*)d_in[6];
    const float* cvw  = (const float*)d_in[7];
    const float* cvb  = (const float*)d_in[8];
    const float* cqw  = (const float*)d_in[9];
    const float* cqb  = (const float*)d_in[10];
    const float* wdec = (const float*)d_in[11];
    const float* bdec = (const float*)d_in[12];
    const float* wlr  = (const float*)d_in[13];
    const float* blr  = (const float*)d_in[14];
    const float* weta = (const float*)d_in[15];
    const float* beta = (const float*)d_in[16];
    const float* W1   = (const float*)d_in[17];
    const float* W2   = (const float*)d_in[18];
    float* out = (float*)d_out;

    float *proj, *kc, *vc, *qc, *ych, *yfl, *a1, *sd, *d1, *tb, *d2;
    float *Wd1, *M1, *Wd2, *M2;
    cudaGetSymbolAddress((void**)&proj, g_proj);
    cudaGetSymbolAddress((void**)&kc,   g_kc);
    cudaGetSymbolAddress((void**)&vc,   g_vc);
    cudaGetSymbolAddress((void**)&qc,   g_qc);
    cudaGetSymbolAddress((void**)&ych,  g_ych);
    cudaGetSymbolAddress((void**)&yfl,  g_yfl);
    cudaGetSymbolAddress((void**)&a1,   g_a1);
    cudaGetSymbolAddress((void**)&sd,   g_sd);
    cudaGetSymbolAddress((void**)&d1,   g_d1);
    cudaGetSymbolAddress((void**)&tb,   g_tb);
    cudaGetSymbolAddress((void**)&d2,   g_d2);
    cudaGetSymbolAddress((void**)&Wd1,  g_Wd1);
    cudaGetSymbolAddress((void**)&M1,   g_M1);
    cudaGetSymbolAddress((void**)&Wd2,  g_Wd2);
    cudaGetSymbolAddress((void**)&M2,   g_M2);

    const int nRD = R_ * D_;
    const int nHD = H_ * D_;
    const int nTOT = BS_ * D_;

    zero_state_kernel<<<(nHD + 255) / 256, 256>>>();
    gates_kernel<<<NC_, 512>>>(x, wdec, bdec, wlr, blr, weta, beta);

    // projections + causal depthwise conv -> chunk-major k,v,q
    run<0, false, false, false>(x, Wk, nullptr, proj, nullptr, nullptr, nullptr, BS_, D_, D_, 0);
    conv_chunk_kernel<<<(nTOT + 255) / 256, 256>>>(proj, ckw, ckb, kc);
    run<0, false, false, false>(x, Wv, nullptr, proj, nullptr, nullptr, nullptr, BS_, D_, D_, 0);
    conv_chunk_kernel<<<(nTOT + 255) / 256, 256>>>(proj, cvw, cvb, vc);
    run<0, false, false, false>(x, Wq, nullptr, proj, nullptr, nullptr, nullptr, BS_, D_, D_, 0);
    conv_chunk_kernel<<<(nTOT + 255) / 256, 256>>>(proj, cqw, cqb, qc);

    // sequential chunk scan — all tensor-core GEMMs with fused epilogues
    for (int c = 0; c < NC_; c++) {
        const float* kcc = kc + (size_t)c * nRD;
        const float* vcc = vc + (size_t)c * nRD;
        const float* qcc = qc + (size_t)c * nRD;

        // h1 = Kc (W1+Wd1)^T -> a1 = silu, sd = silu'
        run<1, false, false, true>(kcc, W1, Wd1, a1, nullptr, sd, nullptr, R_, H_, D_, 0);
        // pred = a1 (W2+Wd2)^T -> d2 = SCALE*clip(pred - v)
        run<2, false, false, true>(a1, W2, Wd2, d2, vcc, nullptr, nullptr, R_, D_, H_, 0);
        // d1 = (d2 (W2+Wd2)) * sd    (B = [K=D][N=H] trans; uses OLD Wd2)
        run<3, false, true, true>(d2, W2, Wd2, d1, sd, nullptr, nullptr, R_, H_, D_, 0);
        // g2[d,h] = sum_r d2[r,d] a1[r,h] -> clipped momentum+decay update of (M2, Wd2)
        run<4, true, true, false>(d2, a1, nullptr, nullptr, nullptr, M2, Wd2, D_, H_, R_, c);
        // g1[h,d] = sum_r d1[r,h] kc[r,d] -> update (M1, Wd1)
        run<4, true, true, false>(d1, kcc, nullptr, nullptr, nullptr, M1, Wd1, H_, D_, R_, c);
        // retrieval: tb = silu(Qc (W1+Wd1)^T);  y = tb (W2+Wd2)^T
        run<5, false, false, true>(qcc, W1, Wd1, tb, nullptr, nullptr, nullptr, R_, H_, D_, 0);
        run<0, false, false, true>(tb, W2, Wd2, ych + (size_t)c * nRD, nullptr, nullptr, nullptr,
                                   R_, D_, H_, 0);
    }

    permute_y_kernel<<<(nTOT + 255) / 256, 256>>>();
    run<0, false, false, false>(yfl, Wout, nullptr, out, nullptr, nullptr, nullptr, BS_, D_, D_, 0);
}

// round 6
// speedup vs baseline: 1.6665x; 1.5895x over previous
#include <cuda_runtime.h>
#include <cuda_bf16.h>
#include <math.h>
#include <stdint.h>

// ---------------- problem dims ----------------
#define B_   8
#define S_   4096
#define D_   512
#define H_   1024
#define Kc_  4
#define CS_  64
#define NC_  64
#define BS_  (B_ * S_)      // 32768 tokens
#define R_   512            // rows per chunk (B*CS)
#define ERR_CLIP  1.0f
#define GRAD_CLIP 1.0f
#define SCALE_    0.03125f  // 2/CS

typedef __nv_bfloat16 bf16;
typedef __nv_bfloat162 bf162;

// ---------------- device scratch ----------------
__device__ float g_proj[(size_t)BS_ * D_];
__device__ float g_vc  [(size_t)BS_ * D_];   // [NC][R][D] fp32 (epilogue operand only)
__device__ float g_ych [(size_t)BS_ * D_];
__device__ float g_sd  [(size_t)R_ * H_];
__device__ float g_Wd1 [(size_t)H_ * D_];
__device__ float g_M1  [(size_t)H_ * D_];
__device__ float g_Wd2 [(size_t)D_ * H_];
__device__ float g_M2  [(size_t)D_ * H_];
__device__ float g_alpha[NC_];
__device__ float g_lrg [NC_];
__device__ float g_eta [NC_];
// bf16 hi/lo operand arrays
__device__ bf16 g_xh [(size_t)BS_ * D_];
__device__ bf16 g_xl [(size_t)BS_ * D_];
__device__ bf16 g_kch[(size_t)BS_ * D_];
__device__ bf16 g_kcl[(size_t)BS_ * D_];
__device__ bf16 g_qch[(size_t)BS_ * D_];
__device__ bf16 g_qcl[(size_t)BS_ * D_];
__device__ bf16 g_yfh[(size_t)BS_ * D_];
__device__ bf16 g_yfl[(size_t)BS_ * D_];
__device__ bf16 g_a1h[(size_t)R_ * H_];
__device__ bf16 g_a1l[(size_t)R_ * H_];
__device__ bf16 g_d2h[(size_t)R_ * D_];
__device__ bf16 g_d2l[(size_t)R_ * D_];
__device__ bf16 g_d1h[(size_t)R_ * H_];
__device__ bf16 g_d1l[(size_t)R_ * H_];
__device__ bf16 g_tbh[(size_t)R_ * H_];
__device__ bf16 g_tbl[(size_t)R_ * H_];
__device__ bf16 g_E1h[(size_t)H_ * D_];
__device__ bf16 g_E1l[(size_t)H_ * D_];
__device__ bf16 g_E2h[(size_t)D_ * H_];
__device__ bf16 g_E2l[(size_t)D_ * H_];
__device__ bf16 g_Wkh[(size_t)D_ * D_];
__device__ bf16 g_Wkl[(size_t)D_ * D_];
__device__ bf16 g_Wvh[(size_t)D_ * D_];
__device__ bf16 g_Wvl[(size_t)D_ * D_];
__device__ bf16 g_Wqh[(size_t)D_ * D_];
__device__ bf16 g_Wql[(size_t)D_ * D_];
__device__ bf16 g_Woh[(size_t)D_ * D_];
__device__ bf16 g_Wol[(size_t)D_ * D_];

// ---------------- helpers ----------------
__device__ __forceinline__ float sigm(float x) { return 1.0f / (1.0f + __expf(-x)); }

__device__ __forceinline__ uint32_t smem_u32(const void* p) {
    uint32_t a;
    asm("{ .reg .u64 t; cvta.to.shared.u64 t, %1; cvt.u32.u64 %0, t; }" : "=r"(a) : "l"(p));
    return a;
}
__device__ __forceinline__ void ldsm4(uint32_t* r, uint32_t a) {
    asm volatile("ldmatrix.sync.aligned.m8n8.x4.shared.b16 {%0,%1,%2,%3}, [%4];"
        : "=r"(r[0]), "=r"(r[1]), "=r"(r[2]), "=r"(r[3]) : "r"(a));
}
__device__ __forceinline__ void ldsm4t(uint32_t* r, uint32_t a) {
    asm volatile("ldmatrix.sync.aligned.m8n8.x4.trans.shared.b16 {%0,%1,%2,%3}, [%4];"
        : "=r"(r[0]), "=r"(r[1]), "=r"(r[2]), "=r"(r[3]) : "r"(a));
}
__device__ __forceinline__ void mma16816(float* c, const uint32_t* a, uint32_t b0, uint32_t b1) {
    asm volatile("mma.sync.aligned.m16n8k16.row.col.f32.bf16.bf16.f32 "
        "{%0,%1,%2,%3}, {%4,%5,%6,%7}, {%8,%9}, {%0,%1,%2,%3};"
        : "+f"(c[0]), "+f"(c[1]), "+f"(c[2]), "+f"(c[3])
        : "r"(a[0]), "r"(a[1]), "r"(a[2]), "r"(a[3]), "r"(b0), "r"(b1));
}
__device__ __forceinline__ void cpa(uint32_t dst, const void* src) {
    asm volatile("cp.async.cg.shared.global [%0], [%1], 16;" :: "r"(dst), "l"(src));
}
#define CP_COMMIT() asm volatile("cp.async.commit_group;" ::: "memory")
#define CP_WAIT(n)  asm volatile("cp.async.wait_group %0;" :: "n"(n) : "memory")

// write fp32 pair as hi/lo bf16 pairs
__device__ __forceinline__ void wr_hl(bf16* Ch, bf16* Cl, size_t idx, float v0, float v1)
{
    bf162 h(__float2bfloat16_rn(v0), __float2bfloat16_rn(v1));
    bf162 l(__float2bfloat16_rn(v0 - __bfloat162float(h.x)),
            __float2bfloat16_rn(v1 - __bfloat162float(h.y)));
    *(bf162*)(Ch + idx) = h;
    *(bf162*)(Cl + idx) = l;
}

// ---------------- tile loader: one 64x64 bf16 tile half via cp.async ----------------
// smem layout: 64 rows x 128B (8 x 16B chunks), chunk c stored at c ^ (row & 7)
// direct (TR=0): src rows = output dim (ld = K);  trans (TR=1): src rows = k (ld = dim)
template <bool TR>
__device__ __forceinline__ void load_tile(uint32_t sbase, const bf16* __restrict__ g,
                                          int org, int ld, int k0, int t)
{
    const int row = t >> 1;
    const int cb = (t & 1) << 2;
    const bf16* src = TR ? (g + (size_t)(k0 + row) * ld + org + cb * 8)
                         : (g + (size_t)(org + row) * ld + k0 + cb * 8);
#pragma unroll
    for (int i = 0; i < 4; i++) {
        const int c = cb + i;
        cpa(sbase + row * 128 + ((c ^ (row & 7)) << 4), src + i * 8);
    }
}

// ---------------- one K=64 chunk of MMAs (3 emulation passes) ----------------
// buffer layout: AH @+0, AL @+8192, BH @+16384, BL @+24576
template <bool AT, bool BT>
__device__ __forceinline__ void mma_chunk(uint32_t ab, float acc[2][4][4],
                                          int wm, int wn, int lane)
{
#pragma unroll
    for (int koi = 0; koi < 4; koi++) {
        const int ko = koi << 4;
        uint32_t ah[2][4], al[2][4], bh[2][4], bl[2][4];
#pragma unroll
        for (int i = 0; i < 2; i++) {
            const int mf = wm * 32 + i * 16;
            uint32_t off;
            if (!AT) {
                const int row = mf + (lane & 7) + ((lane & 8) ? 8 : 0);
                const int ck = (ko >> 3) + ((lane >> 4) & 1);
                off = row * 128 + ((ck ^ (row & 7)) << 4);
                ldsm4(ah[i], ab + off);
                ldsm4(al[i], ab + 8192 + off);
            } else {
                const int row = ko + (lane & 7) + ((lane & 16) ? 8 : 0);
                const int ck = (mf >> 3) + ((lane >> 3) & 1);
                off = row * 128 + ((ck ^ (row & 7)) << 4);
                ldsm4t(ah[i], ab + off);
                ldsm4t(al[i], ab + 8192 + off);
            }
        }
#pragma unroll
        for (int jp = 0; jp < 2; jp++) {
            const int nf = wn * 32 + jp * 16;
            uint32_t off;
            if (!BT) {
                const int row = nf + (lane & 7) + ((lane & 16) ? 8 : 0);
                const int ck = (ko >> 3) + ((lane >> 3) & 1);
                off = row * 128 + ((ck ^ (row & 7)) << 4);
                ldsm4(bh[jp], ab + 16384 + off);
                ldsm4(bl[jp], ab + 24576 + off);
            } else {
                const int row = ko + (lane & 7) + ((lane & 8) ? 8 : 0);
                const int ck = (nf >> 3) + ((lane >> 4) & 1);
                off = row * 128 + ((ck ^ (row & 7)) << 4);
                ldsm4t(bh[jp], ab + 16384 + off);
                ldsm4t(bl[jp], ab + 24576 + off);
            }
        }
#pragma unroll
        for (int i = 0; i < 2; i++)
#pragma unroll
            for (int j = 0; j < 4; j++) {
                const int jp = j >> 1, wv = (j & 1) << 1;
                mma16816(acc[i][j], ah[i], bh[jp][wv], bh[jp][wv + 1]);  // hi*hi
                mma16816(acc[i][j], ah[i], bl[jp][wv], bl[jp][wv + 1]);  // hi*lo
                mma16816(acc[i][j], al[i], bh[jp][wv], bh[jp][wv + 1]);  // lo*hi
            }
    }
}

// ---------------- tensor GEMM: C[M,N] = opA(A) * opB(B), preconverted bf16 hi/lo ------
// AT=0: A is [M,K] ; AT=1: A is [K,M].  BT=0: B is [N,K] ; BT=1: B is [K,N].
// EPI 0: C(fp32) = acc
// EPI 1: Ch/Cl = silu(acc), U1(fp32) = silu'(acc)
// EPI 2: Ch/Cl = SCALE*clip(acc - X1, +-ERR_CLIP)
// EPI 3: Ch/Cl = acc * X1
// EPI 4: g=clip(acc); U1 = eta*U1 - lr*g; U2 = (1-alpha)*U2 + U1; Ch/Cl = X1 + U2new
// EPI 5: Ch/Cl = silu(acc)
template <int EPI, bool AT, bool BT>
__global__ void __launch_bounds__(128)
mma_gemm(const bf16* __restrict__ Ah, const bf16* __restrict__ Al,
         const bf16* __restrict__ Bh, const bf16* __restrict__ Bl,
         float* __restrict__ C, bf16* __restrict__ Ch, bf16* __restrict__ Cl,
         const float* __restrict__ X1, float* __restrict__ U1, float* __restrict__ U2,
         int M, int N, int K, int gate)
{
    extern __shared__ __align__(1024) char smem[];
    const int t = threadIdx.x, lane = t & 31, w = t >> 5;
    const int wm = w & 1, wn = w >> 1;
    const int m0 = blockIdx.y << 6, n0 = blockIdx.x << 6;
    const uint32_t sb = smem_u32(smem);
    const int ldA = AT ? M : K;
    const int ldB = BT ? N : K;

    float acc[2][4][4] = {};
    const int nch = K >> 6;

    // prologue: chunk 0 into buffer 0
    load_tile<AT>(sb,          Ah, m0, ldA, 0, t);
    load_tile<AT>(sb + 8192,   Al, m0, ldA, 0, t);
    load_tile<BT>(sb + 16384,  Bh, n0, ldB, 0, t);
    load_tile<BT>(sb + 24576,  Bl, n0, ldB, 0, t);
    CP_COMMIT();

    for (int ch = 0; ch < nch; ch++) {
        if (ch + 1 < nch) {
            const uint32_t nb = sb + ((ch + 1) & 1) * 32768;
            const int k0 = (ch + 1) << 6;
            load_tile<AT>(nb,          Ah, m0, ldA, k0, t);
            load_tile<AT>(nb + 8192,   Al, m0, ldA, k0, t);
            load_tile<BT>(nb + 16384,  Bh, n0, ldB, k0, t);
            load_tile<BT>(nb + 24576,  Bl, n0, ldB, k0, t);
            CP_COMMIT();
            CP_WAIT(1);
        } else {
            CP_WAIT(0);
        }
        __syncthreads();
        mma_chunk<AT, BT>(sb + (ch & 1) * 32768, acc, wm, wn, lane);
        __syncthreads();
    }

    // ---- epilogue ----
    const float ga = (EPI == 4) ? g_alpha[gate] : 0.f;
    const float gl = (EPI == 4) ? g_lrg[gate] : 0.f;
    const float ge = (EPI == 4) ? g_eta[gate] : 0.f;
#pragma unroll
    for (int i = 0; i < 2; i++)
#pragma unroll
        for (int j = 0; j < 4; j++) {
            const float* a = acc[i][j];
            const int mr0 = m0 + wm * 32 + i * 16 + (lane >> 2);
            const int nc  = n0 + wn * 32 + j * 8 + ((lane & 3) << 1);
            const size_t i0 = (size_t)mr0 * N + nc;
            const size_t i1 = (size_t)(mr0 + 8) * N + nc;

            if (EPI == 0) {
                *(float2*)(C + i0) = make_float2(a[0], a[1]);
                *(float2*)(C + i1) = make_float2(a[2], a[3]);
            } else if (EPI == 1) {
                const float s0 = sigm(a[0]), s1 = sigm(a[1]);
                const float s2 = sigm(a[2]), s3 = sigm(a[3]);
                wr_hl(Ch, Cl, i0, a[0] * s0, a[1] * s1);
                wr_hl(Ch, Cl, i1, a[2] * s2, a[3] * s3);
                *(float2*)(U1 + i0) = make_float2(s0 * (1.f + a[0] * (1.f - s0)),
                                                  s1 * (1.f + a[1] * (1.f - s1)));
                *(float2*)(U1 + i1) = make_float2(s2 * (1.f + a[2] * (1.f - s2)),
                                                  s3 * (1.f + a[3] * (1.f - s3)));
            } else if (EPI == 2) {
                const float2 v0 = *(const float2*)(X1 + i0);
                const float2 v1 = *(const float2*)(X1 + i1);
                wr_hl(Ch, Cl, i0,
                      SCALE_ * fminf(fmaxf(a[0] - v0.x, -ERR_CLIP), ERR_CLIP),
                      SCALE_ * fminf(fmaxf(a[1] - v0.y, -ERR_CLIP), ERR_CLIP));
                wr_hl(Ch, Cl, i1,
                      SCALE_ * fminf(fmaxf(a[2] - v1.x, -ERR_CLIP), ERR_CLIP),
                      SCALE_ * fminf(fmaxf(a[3] - v1.y, -ERR_CLIP), ERR_CLIP));
            } else if (EPI == 3) {
                const float2 v0 = *(const float2*)(X1 + i0);
                const float2 v1 = *(const float2*)(X1 + i1);
                wr_hl(Ch, Cl, i0, a[0] * v0.x, a[1] * v0.y);
                wr_hl(Ch, Cl, i1, a[2] * v1.x, a[3] * v1.y);
            } else if (EPI == 4) {
                float2 mo0 = *(float2*)(U1 + i0), mo1 = *(float2*)(U1 + i1);
                float2 wd0 = *(float2*)(U2 + i0), wd1 = *(float2*)(U2 + i1);
                mo0.x = ge * mo0.x - gl * fminf(fmaxf(a[0], -GRAD_CLIP), GRAD_CLIP);
                mo0.y = ge * mo0.y - gl * fminf(fmaxf(a[1], -GRAD_CLIP), GRAD_CLIP);
                mo1.x = ge * mo1.x - gl * fminf(fmaxf(a[2], -GRAD_CLIP), GRAD_CLIP);
                mo1.y = ge * mo1.y - gl * fminf(fmaxf(a[3], -GRAD_CLIP), GRAD_CLIP);
                wd0.x = (1.f - ga) * wd0.x + mo0.x;
                wd0.y = (1.f - ga) * wd0.y + mo0.y;
                wd1.x = (1.f - ga) * wd1.x + mo1.x;
                wd1.y = (1.f - ga) * wd1.y + mo1.y;
                *(float2*)(U1 + i0) = mo0; *(float2*)(U1 + i1) = mo1;
                *(float2*)(U2 + i0) = wd0; *(float2*)(U2 + i1) = wd1;
                const float2 w0 = *(const float2*)(X1 + i0);
                const float2 w1 = *(const float2*)(X1 + i1);
                wr_hl(Ch, Cl, i0, w0.x + wd0.x, w0.y + wd0.y);
                wr_hl(Ch, Cl, i1, w1.x + wd1.x, w1.y + wd1.y);
            } else { // EPI 5
                wr_hl(Ch, Cl, i0, a[0] * sigm(a[0]), a[1] * sigm(a[1]));
                wr_hl(Ch, Cl, i1, a[2] * sigm(a[2]), a[3] * sigm(a[3]));
            }
        }
}

#define GSMEM 65536

template <int EPI, bool AT, bool BT>
static void run(const bf16* Ah, const bf16* Al, const bf16* Bh, const bf16* Bl,
                float* C, bf16* Ch, bf16* Cl,
                const float* X1, float* U1, float* U2, int M, int N, int K, int gate)
{
    cudaFuncSetAttribute(mma_gemm<EPI, AT, BT>,
                         cudaFuncAttributeMaxDynamicSharedMemorySize, GSMEM);
    dim3 grid(N >> 6, M >> 6);
    mma_gemm<EPI, AT, BT><<<grid, 128, GSMEM>>>(Ah, Al, Bh, Bl, C, Ch, Cl, X1, U1, U2,
                                                M, N, K, gate);
}

// ---------------- misc kernels ----------------
// zero optimizer state; E1 = W1 split, E2 = W2 split
__global__ void init_kernel(const float* __restrict__ W1, const float* __restrict__ W2)
{
    const size_t i = ((size_t)blockIdx.x * blockDim.x + threadIdx.x) * 2;
    if (i >= (size_t)H_ * D_) return;
    *(float2*)(g_Wd1 + i) = make_float2(0.f, 0.f);
    *(float2*)(g_M1  + i) = make_float2(0.f, 0.f);
    *(float2*)(g_Wd2 + i) = make_float2(0.f, 0.f);
    *(float2*)(g_M2  + i) = make_float2(0.f, 0.f);
    const float2 w1 = *(const float2*)(W1 + i);
    const float2 w2 = *(const float2*)(W2 + i);
    wr_hl(g_E1h, g_E1l, i, w1.x, w1.y);
    wr_hl(g_E2h, g_E2l, i, w2.x, w2.y);
}

__global__ void cvt_kernel(const float* __restrict__ s, bf16* __restrict__ h,
                           bf16* __restrict__ l, int n2)
{
    const int i = blockIdx.x * blockDim.x + threadIdx.x;
    if (i >= n2) return;
    const float2 v = ((const float2*)s)[i];
    wr_hl(h, l, (size_t)i * 2, v.x, v.y);
}

// causal depthwise conv -> chunk-major [NC][R][D]; writes hi/lo bf16 OR fp32
__global__ void conv_chunk_kernel(const float* __restrict__ in, const float* __restrict__ w,
                                  const float* __restrict__ bias,
                                  bf16* __restrict__ oh, bf16* __restrict__ ol,
                                  float* __restrict__ of)
{
    const size_t i = (size_t)blockIdx.x * blockDim.x + threadIdx.x;
    if (i >= (size_t)BS_ * D_) return;
    const int d = (int)(i & (D_ - 1));
    const size_t bs = i >> 9;
    const int s = (int)(bs & (S_ - 1));
    const int b = (int)(bs >> 12);
    float acc = bias[d];
#pragma unroll
    for (int j = 0; j < Kc_; j++) {
        const int sp = s - (Kc_ - 1) + j;
        if (sp >= 0)
            acc = fmaf(w[d * Kc_ + j], in[((size_t)b * S_ + sp) * D_ + d], acc);
    }
    const int c  = s >> 6;
    const int cs = s & 63;
    const size_t o = (((size_t)c * R_ + (b * CS_ + cs)) << 9) + d;
    if (of) {
        of[o] = acc;
    } else {
        const bf16 hv = __float2bfloat16_rn(acc);
        oh[o] = hv;
        ol[o] = __float2bfloat16_rn(acc - __bfloat162float(hv));
    }
}

__global__ void gates_kernel(const float* __restrict__ x,
                             const float* __restrict__ wd, const float* __restrict__ bd,
                             const float* __restrict__ wl, const float* __restrict__ bl,
                             const float* __restrict__ we, const float* __restrict__ be)
{
    const int c = blockIdx.x;
    const int t = threadIdx.x;          // 0..511
    const int b  = t >> 6;
    const int cs = t & 63;
    const float4* xr = (const float4*)(x + (((size_t)b * S_ + (size_t)c * CS_ + cs) << 9));
    const float4* w0 = (const float4*)wd;
    const float4* w1 = (const float4*)wl;
    const float4* w2 = (const float4*)we;
    float s0 = 0.f, s1 = 0.f, s2 = 0.f;
#pragma unroll 4
    for (int d = 0; d < D_ / 4; d++) {
        const float4 xv = xr[d];
        const float4 a0 = w0[d], a1 = w1[d], a2 = w2[d];
        s0 += xv.x * a0.x + xv.y * a0.y + xv.z * a0.z + xv.w * a0.w;
        s1 += xv.x * a1.x + xv.y * a1.y + xv.z * a1.z + xv.w * a1.w;
        s2 += xv.x * a2.x + xv.y * a2.y + xv.z * a2.z + xv.w * a2.w;
    }
    s0 = sigm(s0 + bd[0]);
    s1 = sigm(s1 + bl[0]);
    s2 = sigm(s2 + be[0]);

    __shared__ float r0[512], r1[512], r2[512];
    r0[t] = s0; r1[t] = s1; r2[t] = s2;
    __syncthreads();
    for (int off = 256; off > 0; off >>= 1) {
        if (t < off) { r0[t] += r0[t + off]; r1[t] += r1[t + off]; r2[t] += r2[t + off]; }
        __syncthreads();
    }
    if (t == 0) {
        g_alpha[c] = r0[0] * (1.0f / 512.0f);
        g_lrg[c]   = r1[0] * (1.0f / 512.0f);
        g_eta[c]   = r2[0] * (1.0f / 512.0f);
    }
}

// chunk-major ych -> flat [B,S,D] as bf16 hi/lo
__global__ void permute_y_kernel()
{
    const size_t i = (size_t)blockIdx.x * blockDim.x + threadIdx.x;
    if (i >= (size_t)BS_ * D_) return;
    const int d = (int)(i & (D_ - 1));
    const size_t rw = i >> 9;
    const int s = (int)(rw & (S_ - 1));
    const int b = (int)(rw >> 12);
    const int c  = s >> 6;
    const int cs = s & 63;
    const float v = g_ych[(((size_t)c * R_ + (b * CS_ + cs)) << 9) + d];
    const bf16 hv = __float2bfloat16_rn(v);
    g_yfh[i] = hv;
    g_yfl[i] = __float2bfloat16_rn(v - __bfloat162float(hv));
}

// ---------------- entry point ----------------
extern "C" void kernel_launch(void* const* d_in, const int* in_sizes, int n_in,
                              void* d_out, int out_size)
{
    (void)in_sizes; (void)n_in; (void)out_size;
    const float* x    = (const float*)d_in[0];
    const float* Wk   = (const float*)d_in[1];
    const float* Wv   = (const float*)d_in[2];
    const float* Wq   = (const float*)d_in[3];
    const float* Wout = (const float*)d_in[4];
    const float* ckw  = (const float*)d_in[5];
    const float* ckb  = (const float*)d_in[6];
    const float* cvw  = (const float*)d_in[7];
    const float* cvb  = (const float*)d_in[8];
    const float* cqw  = (const float*)d_in[9];
    const float* cqb  = (const float*)d_in[10];
    const float* wdec = (const float*)d_in[11];
    const float* bdec = (const float*)d_in[12];
    const float* wlr  = (const float*)d_in[13];
    const float* blr  = (const float*)d_in[14];
    const float* weta = (const float*)d_in[15];
    const float* beta = (const float*)d_in[16];
    const float* W1   = (const float*)d_in[17];
    const float* W2   = (const float*)d_in[18];
    float* out = (float*)d_out;

    float *proj, *vc, *ych, *sd, *Wd1, *M1, *Wd2, *M2;
    bf16 *xh, *xl, *kch, *kcl, *qch, *qcl, *yfh, *yfl;
    bf16 *a1h, *a1l, *d2h, *d2l, *d1h, *d1l, *tbh, *tbl;
    bf16 *E1h, *E1l, *E2h, *E2l, *Wkh, *Wkl, *Wvh, *Wvl, *Wqh, *Wql, *Woh, *Wol;
    cudaGetSymbolAddress((void**)&proj, g_proj);
    cudaGetSymbolAddress((void**)&vc,   g_vc);
    cudaGetSymbolAddress((void**)&ych,  g_ych);
    cudaGetSymbolAddress((void**)&sd,   g_sd);
    cudaGetSymbolAddress((void**)&Wd1,  g_Wd1);
    cudaGetSymbolAddress((void**)&M1,   g_M1);
    cudaGetSymbolAddress((void**)&Wd2,  g_Wd2);
    cudaGetSymbolAddress((void**)&M2,   g_M2);
    cudaGetSymbolAddress((void**)&xh,  g_xh);  cudaGetSymbolAddress((void**)&xl,  g_xl);
    cudaGetSymbolAddress((void**)&kch, g_kch); cudaGetSymbolAddress((void**)&kcl, g_kcl);
    cudaGetSymbolAddress((void**)&qch, g_qch); cudaGetSymbolAddress((void**)&qcl, g_qcl);
    cudaGetSymbolAddress((void**)&yfh, g_yfh); cudaGetSymbolAddress((void**)&yfl, g_yfl);
    cudaGetSymbolAddress((void**)&a1h, g_a1h); cudaGetSymbolAddress((void**)&a1l, g_a1l);
    cudaGetSymbolAddress((void**)&d2h, g_d2h); cudaGetSymbolAddress((void**)&d2l, g_d2l);
    cudaGetSymbolAddress((void**)&d1h, g_d1h); cudaGetSymbolAddress((void**)&d1l, g_d1l);
    cudaGetSymbolAddress((void**)&tbh, g_tbh); cudaGetSymbolAddress((void**)&tbl, g_tbl);
    cudaGetSymbolAddress((void**)&E1h, g_E1h); cudaGetSymbolAddress((void**)&E1l, g_E1l);
    cudaGetSymbolAddress((void**)&E2h, g_E2h); cudaGetSymbolAddress((void**)&E2l, g_E2l);
    cudaGetSymbolAddress((void**)&Wkh, g_Wkh); cudaGetSymbolAddress((void**)&Wkl, g_Wkl);
    cudaGetSymbolAddress((void**)&Wvh, g_Wvh); cudaGetSymbolAddress((void**)&Wvl, g_Wvl);
    cudaGetSymbolAddress((void**)&Wqh, g_Wqh); cudaGetSymbolAddress((void**)&Wql, g_Wql);
    cudaGetSymbolAddress((void**)&Woh, g_Woh); cudaGetSymbolAddress((void**)&Wol, g_Wol);

    const int nRD = R_ * D_;
    const int nHD = H_ * D_;
    const int nTOT = BS_ * D_;
    const int nDD = D_ * D_;

    init_kernel<<<(nHD / 2 + 255) / 256, 256>>>(W1, W2);
    gates_kernel<<<NC_, 512>>>(x, wdec, bdec, wlr, blr, weta, beta);

    // preconvert inputs and weights to bf16 hi/lo
    cvt_kernel<<<(nTOT / 2 + 255) / 256, 256>>>(x, xh, xl, nTOT / 2);
    cvt_kernel<<<(nDD / 2 + 255) / 256, 256>>>(Wk, Wkh, Wkl, nDD / 2);
    cvt_kernel<<<(nDD / 2 + 255) / 256, 256>>>(Wv, Wvh, Wvl, nDD / 2);
    cvt_kernel<<<(nDD / 2 + 255) / 256, 256>>>(Wq, Wqh, Wql, nDD / 2);
    cvt_kernel<<<(nDD / 2 + 255) / 256, 256>>>(Wout, Woh, Wol, nDD / 2);

    // projections + causal depthwise conv -> chunk-major k,q (bf16 hi/lo), v (fp32)
    run<0, false, false>(xh, xl, Wkh, Wkl, proj, nullptr, nullptr, nullptr, nullptr, nullptr,
                         BS_, D_, D_, 0);
    conv_chunk_kernel<<<(nTOT + 255) / 256, 256>>>(proj, ckw, ckb, kch, kcl, nullptr);
    run<0, false, false>(xh, xl, Wvh, Wvl, proj, nullptr, nullptr, nullptr, nullptr, nullptr,
                         BS_, D_, D_, 0);
    conv_chunk_kernel<<<(nTOT + 255) / 256, 256>>>(proj, cvw, cvb, nullptr, nullptr, vc);
    run<0, false, false>(xh, xl, Wqh, Wql, proj, nullptr, nullptr, nullptr, nullptr, nullptr,
                         BS_, D_, D_, 0);
    conv_chunk_kernel<<<(nTOT + 255) / 256, 256>>>(proj, cqw, cqb, qch, qcl, nullptr);

    // sequential chunk scan — all tensor GEMMs, pure bf16 loads, fused epilogues
    for (int c = 0; c < NC_; c++) {
        const size_t off = (size_t)c * nRD;

        // h1 = Kc E1^T -> a1 hi/lo + sd
        run<1, false, false>(kch + off, kcl + off, E1h, E1l, nullptr, a1h, a1l,
                             nullptr, sd, nullptr, R_, H_, D_, 0);
        // pred = a1 E2^T -> d2 = SCALE*clip(pred - v) hi/lo
        run<2, false, false>(a1h, a1l, E2h, E2l, nullptr, d2h, d2l,
                             vc + off, nullptr, nullptr, R_, D_, H_, 0);
        // d1 = (d2 E2) * sd -> hi/lo   (B = E2 [D,H] read trans; OLD E2)
        run<3, false, true>(d2h, d2l, E2h, E2l, nullptr, d1h, d1l,
                            sd, nullptr, nullptr, R_, H_, D_, 0);
        // g2[d,h] = d2^T a1 -> update M2/Wd2, emit E2 = W2 + Wd2 hi/lo
        run<4, true, true>(d2h, d2l, a1h, a1l, nullptr, E2h, E2l,
                           W2, M2, Wd2, D_, H_, R_, c);
        // g1[h,d] = d1^T Kc -> update M1/Wd1, emit E1 = W1 + Wd1 hi/lo
        run<4, true, true>(d1h, d1l, kch + off, kcl + off, nullptr, E1h, E1l,
                           W1, M1, Wd1, H_, D_, R_, c);
        // retrieval: tb = silu(Qc E1^T);  y = tb E2^T
        run<5, false, false>(qch + off, qcl + off, E1h, E1l, nullptr, tbh, tbl,
                             nullptr, nullptr, nullptr, R_, H_, D_, 0);
        run<0, false, false>(tbh, tbl, E2h, E2l, ych + off, nullptr, nullptr,
                             nullptr, nullptr, nullptr, R_, D_, H_, 0);
    }

    permute_y_kernel<<<(nTOT + 255) / 256, 256>>>();
    run<0, false, false>(yfh, yfl, Woh, Wol, out, nullptr, nullptr, nullptr, nullptr, nullptr,
                         BS_, D_, D_, 0);
}

// round 7
// speedup vs baseline: 2.2159x; 1.3297x over previous
#include <cuda_runtime.h>
#include <cuda_bf16.h>
#include <math.h>
#include <stdint.h>

// ---------------- problem dims ----------------
#define B_   8
#define S_   4096
#define D_   512
#define H_   1024
#define Kc_  4
#define CS_  64
#define NC_  64
#define BS_  (B_ * S_)      // 32768 tokens
#define R_   512            // rows per chunk (B*CS)
#define ERR_CLIP  1.0f
#define GRAD_CLIP 1.0f
#define SCALE_    0.03125f  // 2/CS

typedef __nv_bfloat16 bf16;
typedef __nv_bfloat162 bf162;

// ---------------- device scratch ----------------
__device__ float g_proj[(size_t)BS_ * D_];
__device__ float g_vc  [(size_t)BS_ * D_];
__device__ float g_ych [(size_t)BS_ * D_];
__device__ float g_sd  [(size_t)R_ * H_];
__device__ float g_Wd1 [(size_t)H_ * D_];
__device__ float g_M1  [(size_t)H_ * D_];
__device__ float g_Wd2 [(size_t)D_ * H_];
__device__ float g_M2  [(size_t)D_ * H_];
__device__ float g_alpha[NC_];
__device__ float g_lrg [NC_];
__device__ float g_eta [NC_];
__device__ bf16 g_xh [(size_t)BS_ * D_];
__device__ bf16 g_xl [(size_t)BS_ * D_];
__device__ bf16 g_kch[(size_t)BS_ * D_];
__device__ bf16 g_kcl[(size_t)BS_ * D_];
__device__ bf16 g_qch[(size_t)BS_ * D_];
__device__ bf16 g_qcl[(size_t)BS_ * D_];
__device__ bf16 g_yfh[(size_t)BS_ * D_];
__device__ bf16 g_yfl[(size_t)BS_ * D_];
__device__ bf16 g_a1h[(size_t)R_ * H_];
__device__ bf16 g_a1l[(size_t)R_ * H_];
__device__ bf16 g_d2h[(size_t)R_ * D_];
__device__ bf16 g_d2l[(size_t)R_ * D_];
__device__ bf16 g_d1h[(size_t)R_ * H_];
__device__ bf16 g_d1l[(size_t)R_ * H_];
__device__ bf16 g_tbh[(size_t)R_ * H_];
__device__ bf16 g_tbl[(size_t)R_ * H_];
__device__ bf16 g_E1h[(size_t)H_ * D_];
__device__ bf16 g_E1l[(size_t)H_ * D_];
__device__ bf16 g_E2h[(size_t)D_ * H_];
__device__ bf16 g_E2l[(size_t)D_ * H_];
__device__ bf16 g_Wkh[(size_t)D_ * D_];
__device__ bf16 g_Wkl[(size_t)D_ * D_];
__device__ bf16 g_Wvh[(size_t)D_ * D_];
__device__ bf16 g_Wvl[(size_t)D_ * D_];
__device__ bf16 g_Wqh[(size_t)D_ * D_];
__device__ bf16 g_Wql[(size_t)D_ * D_];
__device__ bf16 g_Woh[(size_t)D_ * D_];
__device__ bf16 g_Wol[(size_t)D_ * D_];

// ---------------- helpers ----------------
__device__ __forceinline__ float sigm(float x) { return 1.0f / (1.0f + __expf(-x)); }

__device__ __forceinline__ uint32_t smem_u32(const void* p) {
    uint32_t a;
    asm("{ .reg .u64 t; cvta.to.shared.u64 t, %1; cvt.u32.u64 %0, t; }" : "=r"(a) : "l"(p));
    return a;
}
__device__ __forceinline__ void ldsm4(uint32_t* r, uint32_t a) {
    asm volatile("ldmatrix.sync.aligned.m8n8.x4.shared.b16 {%0,%1,%2,%3}, [%4];"
        : "=r"(r[0]), "=r"(r[1]), "=r"(r[2]), "=r"(r[3]) : "r"(a));
}
__device__ __forceinline__ void ldsm4t(uint32_t* r, uint32_t a) {
    asm volatile("ldmatrix.sync.aligned.m8n8.x4.trans.shared.b16 {%0,%1,%2,%3}, [%4];"
        : "=r"(r[0]), "=r"(r[1]), "=r"(r[2]), "=r"(r[3]) : "r"(a));
}
__device__ __forceinline__ void mma16816(float* c, const uint32_t* a, uint32_t b0, uint32_t b1) {
    asm volatile("mma.sync.aligned.m16n8k16.row.col.f32.bf16.bf16.f32 "
        "{%0,%1,%2,%3}, {%4,%5,%6,%7}, {%8,%9}, {%0,%1,%2,%3};"
        : "+f"(c[0]), "+f"(c[1]), "+f"(c[2]), "+f"(c[3])
        : "r"(a[0]), "r"(a[1]), "r"(a[2]), "r"(a[3]), "r"(b0), "r"(b1));
}
__device__ __forceinline__ void cpa(uint32_t dst, const void* src) {
    asm volatile("cp.async.cg.shared.global [%0], [%1], 16;" :: "r"(dst), "l"(src));
}
#define CP_COMMIT() asm volatile("cp.async.commit_group;" ::: "memory")
#define CP_WAIT(n)  asm volatile("cp.async.wait_group %0;" :: "n"(n) : "memory")

__device__ __forceinline__ void wr_hl(bf16* Ch, bf16* Cl, size_t idx, float v0, float v1)
{
    bf162 h(__float2bfloat16_rn(v0), __float2bfloat16_rn(v1));
    bf162 l(__float2bfloat16_rn(v0 - __bfloat162float(h.x)),
            __float2bfloat16_rn(v1 - __bfloat162float(h.y)));
    *(bf162*)(Ch + idx) = h;
    *(bf162*)(Cl + idx) = l;
}

// ---------------- tile loader ----------------
template <bool TR>
__device__ __forceinline__ void load_tile(uint32_t sbase, const bf16* __restrict__ g,
                                          int org, int ld, int k0, int t)
{
    const int row = t >> 1;
    const int cb = (t & 1) << 2;
    const bf16* src = TR ? (g + (size_t)(k0 + row) * ld + org + cb * 8)
                         : (g + (size_t)(org + row) * ld + k0 + cb * 8);
#pragma unroll
    for (int i = 0; i < 4; i++) {
        const int c = cb + i;
        cpa(sbase + row * 128 + ((c ^ (row & 7)) << 4), src + i * 8);
    }
}

// ---------------- one K=64 chunk of MMAs (3 emulation passes) ----------------
template <bool AT, bool BT>
__device__ __forceinline__ void mma_chunk(uint32_t ab, float acc[2][4][4],
                                          int wm, int wn, int lane)
{
#pragma unroll
    for (int koi = 0; koi < 4; koi++) {
        const int ko = koi << 4;
        uint32_t ah[2][4], al[2][4], bh[2][4], bl[2][4];
#pragma unroll
        for (int i = 0; i < 2; i++) {
            const int mf = wm * 32 + i * 16;
            uint32_t off;
            if (!AT) {
                const int row = mf + (lane & 7) + ((lane & 8) ? 8 : 0);
                const int ck = (ko >> 3) + ((lane >> 4) & 1);
                off = row * 128 + ((ck ^ (row & 7)) << 4);
                ldsm4(ah[i], ab + off);
                ldsm4(al[i], ab + 8192 + off);
            } else {
                const int row = ko + (lane & 7) + ((lane & 16) ? 8 : 0);
                const int ck = (mf >> 3) + ((lane >> 3) & 1);
                off = row * 128 + ((ck ^ (row & 7)) << 4);
                ldsm4t(ah[i], ab + off);
                ldsm4t(al[i], ab + 8192 + off);
            }
        }
#pragma unroll
        for (int jp = 0; jp < 2; jp++) {
            const int nf = wn * 32 + jp * 16;
            uint32_t off;
            if (!BT) {
                const int row = nf + (lane & 7) + ((lane & 16) ? 8 : 0);
                const int ck = (ko >> 3) + ((lane >> 3) & 1);
                off = row * 128 + ((ck ^ (row & 7)) << 4);
                ldsm4(bh[jp], ab + 16384 + off);
                ldsm4(bl[jp], ab + 24576 + off);
            } else {
                const int row = ko + (lane & 7) + ((lane & 8) ? 8 : 0);
                const int ck = (nf >> 3) + ((lane >> 4) & 1);
                off = row * 128 + ((ck ^ (row & 7)) << 4);
                ldsm4t(bh[jp], ab + 16384 + off);
                ldsm4t(bl[jp], ab + 24576 + off);
            }
        }
#pragma unroll
        for (int i = 0; i < 2; i++)
#pragma unroll
            for (int j = 0; j < 4; j++) {
                const int jp = j >> 1, wv = (j & 1) << 1;
                mma16816(acc[i][j], ah[i], bh[jp][wv], bh[jp][wv + 1]);
                mma16816(acc[i][j], ah[i], bl[jp][wv], bl[jp][wv + 1]);
                mma16816(acc[i][j], al[i], bh[jp][wv], bh[jp][wv + 1]);
            }
    }
}

// ---------------- GEMM mainloop (double-buffered cp.async) ----------------
template <bool AT, bool BT>
__device__ __forceinline__ void gemm_main(
    const bf16* __restrict__ Ah, const bf16* __restrict__ Al,
    const bf16* __restrict__ Bh, const bf16* __restrict__ Bl,
    int m0, int n0, int ldA, int ldB, int K,
    uint32_t sb, int t, int wm, int wn, int lane, float acc[2][4][4])
{
    const int nch = K >> 6;
    load_tile<AT>(sb,          Ah, m0, ldA, 0, t);
    load_tile<AT>(sb + 8192,   Al, m0, ldA, 0, t);
    load_tile<BT>(sb + 16384,  Bh, n0, ldB, 0, t);
    load_tile<BT>(sb + 24576,  Bl, n0, ldB, 0, t);
    CP_COMMIT();

    for (int ch = 0; ch < nch; ch++) {
        if (ch + 1 < nch) {
            const uint32_t nb = sb + ((ch + 1) & 1) * 32768;
            const int k0 = (ch + 1) << 6;
            load_tile<AT>(nb,          Ah, m0, ldA, k0, t);
            load_tile<AT>(nb + 8192,   Al, m0, ldA, k0, t);
            load_tile<BT>(nb + 16384,  Bh, n0, ldB, k0, t);
            load_tile<BT>(nb + 24576,  Bl, n0, ldB, k0, t);
            CP_COMMIT();
            CP_WAIT(1);
        } else {
            CP_WAIT(0);
        }
        __syncthreads();
        mma_chunk<AT, BT>(sb + (ch & 1) * 32768, acc, wm, wn, lane);
        __syncthreads();
    }
}

// ---------------- epilogues ----------------
// EPI 0: C(fp32) = acc
// EPI 1: Ch/Cl = silu(acc), U1 = silu'(acc)
// EPI 2: Ch/Cl = SCALE*clip(acc - X1)
// EPI 3: Ch/Cl = acc * X1
// EPI 4: g=clip(acc); U1 = eta*U1 - lr*g; U2 = (1-a)*U2 + U1; Ch/Cl = X1 + U2new
// EPI 5: Ch/Cl = silu(acc)
template <int EPI>
__device__ __forceinline__ void epi_store(const float acc[2][4][4],
    int m0, int n0, int N, int wm, int wn, int lane,
    float* __restrict__ C, bf16* __restrict__ Ch, bf16* __restrict__ Cl,
    const float* __restrict__ X1, float* __restrict__ U1, float* __restrict__ U2,
    float ga, float gl, float ge)
{
#pragma unroll
    for (int i = 0; i < 2; i++)
#pragma unroll
        for (int j = 0; j < 4; j++) {
            const float* a = acc[i][j];
            const int mr0 = m0 + wm * 32 + i * 16 + (lane >> 2);
            const int nc  = n0 + wn * 32 + j * 8 + ((lane & 3) << 1);
            const size_t i0 = (size_t)mr0 * N + nc;
            const size_t i1 = (size_t)(mr0 + 8) * N + nc;

            if (EPI == 0) {
                *(float2*)(C + i0) = make_float2(a[0], a[1]);
                *(float2*)(C + i1) = make_float2(a[2], a[3]);
            } else if (EPI == 1) {
                const float s0 = sigm(a[0]), s1 = sigm(a[1]);
                const float s2 = sigm(a[2]), s3 = sigm(a[3]);
                wr_hl(Ch, Cl, i0, a[0] * s0, a[1] * s1);
                wr_hl(Ch, Cl, i1, a[2] * s2, a[3] * s3);
                *(float2*)(U1 + i0) = make_float2(s0 * (1.f + a[0] * (1.f - s0)),
                                                  s1 * (1.f + a[1] * (1.f - s1)));
                *(float2*)(U1 + i1) = make_float2(s2 * (1.f + a[2] * (1.f - s2)),
                                                  s3 * (1.f + a[3] * (1.f - s3)));
            } else if (EPI == 2) {
                const float2 v0 = *(const float2*)(X1 + i0);
                const float2 v1 = *(const float2*)(X1 + i1);
                wr_hl(Ch, Cl, i0,
                      SCALE_ * fminf(fmaxf(a[0] - v0.x, -ERR_CLIP), ERR_CLIP),
                      SCALE_ * fminf(fmaxf(a[1] - v0.y, -ERR_CLIP), ERR_CLIP));
                wr_hl(Ch, Cl, i1,
                      SCALE_ * fminf(fmaxf(a[2] - v1.x, -ERR_CLIP), ERR_CLIP),
                      SCALE_ * fminf(fmaxf(a[3] - v1.y, -ERR_CLIP), ERR_CLIP));
            } else if (EPI == 3) {
                const float2 v0 = *(const float2*)(X1 + i0);
                const float2 v1 = *(const float2*)(X1 + i1);
                wr_hl(Ch, Cl, i0, a[0] * v0.x, a[1] * v0.y);
                wr_hl(Ch, Cl, i1, a[2] * v1.x, a[3] * v1.y);
            } else if (EPI == 4) {
                float2 mo0 = *(float2*)(U1 + i0), mo1 = *(float2*)(U1 + i1);
                float2 wd0 = *(float2*)(U2 + i0), wd1 = *(float2*)(U2 + i1);
                mo0.x = ge * mo0.x - gl * fminf(fmaxf(a[0], -GRAD_CLIP), GRAD_CLIP);
                mo0.y = ge * mo0.y - gl * fminf(fmaxf(a[1], -GRAD_CLIP), GRAD_CLIP);
                mo1.x = ge * mo1.x - gl * fminf(fmaxf(a[2], -GRAD_CLIP), GRAD_CLIP);
                mo1.y = ge * mo1.y - gl * fminf(fmaxf(a[3], -GRAD_CLIP), GRAD_CLIP);
                wd0.x = (1.f - ga) * wd0.x + mo0.x;
                wd0.y = (1.f - ga) * wd0.y + mo0.y;
                wd1.x = (1.f - ga) * wd1.x + mo1.x;
                wd1.y = (1.f - ga) * wd1.y + mo1.y;
                *(float2*)(U1 + i0) = mo0; *(float2*)(U1 + i1) = mo1;
                *(float2*)(U2 + i0) = wd0; *(float2*)(U2 + i1) = wd1;
                const float2 w0 = *(const float2*)(X1 + i0);
                const float2 w1 = *(const float2*)(X1 + i1);
                wr_hl(Ch, Cl, i0, w0.x + wd0.x, w0.y + wd0.y);
                wr_hl(Ch, Cl, i1, w1.x + wd1.x, w1.y + wd1.y);
            } else { // EPI 5
                wr_hl(Ch, Cl, i0, a[0] * sigm(a[0]), a[1] * sigm(a[1]));
                wr_hl(Ch, Cl, i1, a[2] * sigm(a[2]), a[3] * sigm(a[3]));
            }
        }
}

#define GSMEM 65536

// ---------------- solo GEMM kernel ----------------
template <int EPI, bool AT, bool BT>
__global__ void __launch_bounds__(128)
mma_gemm(const bf16* __restrict__ Ah, const bf16* __restrict__ Al,
         const bf16* __restrict__ Bh, const bf16* __restrict__ Bl,
         float* __restrict__ C, bf16* __restrict__ Ch, bf16* __restrict__ Cl,
         const float* __restrict__ X1, float* __restrict__ U1, float* __restrict__ U2,
         int M, int N, int K, int gate)
{
    extern __shared__ __align__(1024) char smem[];
    const int t = threadIdx.x, lane = t & 31, w = t >> 5;
    const int wm = w & 1, wn = w >> 1;
    const int m0 = blockIdx.y << 6, n0 = blockIdx.x << 6;
    const uint32_t sb = smem_u32(smem);
    float acc[2][4][4] = {};
    gemm_main<AT, BT>(Ah, Al, Bh, Bl, m0, n0, AT ? M : K, BT ? N : K, K,
                      sb, t, wm, wn, lane, acc);
    const float ga = (EPI == 4) ? g_alpha[gate] : 0.f;
    const float gl = (EPI == 4) ? g_lrg[gate] : 0.f;
    const float ge = (EPI == 4) ? g_eta[gate] : 0.f;
    epi_store<EPI>(acc, m0, n0, N, wm, wn, lane, C, Ch, Cl, X1, U1, U2, ga, gl, ge);
}

// ---------------- dual-segment GEMM: shared B, A split by row block ----------------
// segment a: rows [0, Ma) -> EPIa ; segment b: rows [Ma, Ma+Mb) -> EPIb
template <int EPIa, int EPIb>
__global__ void __launch_bounds__(128)
mma_gemm_dual(const bf16* __restrict__ Aah, const bf16* __restrict__ Aal,
              const bf16* __restrict__ Abh, const bf16* __restrict__ Abl, int Ma,
              const bf16* __restrict__ Bh, const bf16* __restrict__ Bl,
              float* __restrict__ Ca, bf16* __restrict__ Cah, bf16* __restrict__ Cal,
              const float* __restrict__ X1a, float* __restrict__ U1a,
              float* __restrict__ Cb, bf16* __restrict__ Cbh, bf16* __restrict__ Cbl,
              const float* __restrict__ X1b, float* __restrict__ U1b,
              int N, int K)
{
    extern __shared__ __align__(1024) char smem[];
    const int t = threadIdx.x, lane = t & 31, w = t >> 5;
    const int wm = w & 1, wn = w >> 1;
    const int ya = Ma >> 6;
    const bool segb = (int)blockIdx.y >= ya;
    const bf16* Ah = segb ? Abh : Aah;
    const bf16* Al = segb ? Abl : Aal;
    const int m0 = (segb ? ((int)blockIdx.y - ya) : (int)blockIdx.y) << 6;
    const int n0 = blockIdx.x << 6;
    const uint32_t sb = smem_u32(smem);
    float acc[2][4][4] = {};
    gemm_main<false, false>(Ah, Al, Bh, Bl, m0, n0, K, K, K, sb, t, wm, wn, lane, acc);
    if (!segb)
        epi_store<EPIa>(acc, m0, n0, N, wm, wn, lane, Ca, Cah, Cal, X1a, U1a, nullptr,
                        0.f, 0.f, 0.f);
    else
        epi_store<EPIb>(acc, m0, n0, N, wm, wn, lane, Cb, Cbh, Cbl, X1b, U1b, nullptr,
                        0.f, 0.f, 0.f);
}

// ---------------- fused dual-update kernel: g2-update + g1-update ----------------
// seg a (bid<128): M=D(512), N=H(1024): A=d2 [R,D] trans, B=a1 [R,H] trans
// seg b          : M=H(1024), N=D(512): A=d1 [R,H] trans, B=kc [R,D] trans
__global__ void __launch_bounds__(128)
mma_update_dual(const bf16* __restrict__ d2h, const bf16* __restrict__ d2l,
                const bf16* __restrict__ a1h, const bf16* __restrict__ a1l,
                const bf16* __restrict__ d1h, const bf16* __restrict__ d1l,
                const bf16* __restrict__ kchp, const bf16* __restrict__ kclp,
                const float* __restrict__ W2, float* __restrict__ M2,
                float* __restrict__ Wd2, bf16* __restrict__ E2h, bf16* __restrict__ E2l,
                const float* __restrict__ W1, float* __restrict__ M1,
                float* __restrict__ Wd1, bf16* __restrict__ E1h, bf16* __restrict__ E1l,
                int gate)
{
    extern __shared__ __align__(1024) char smem[];
    const int t = threadIdx.x, lane = t & 31, w = t >> 5;
    const int wm = w & 1, wn = w >> 1;
    const int bid = blockIdx.x;
    const bool segb = bid >= 128;
    const uint32_t sb = smem_u32(smem);
    const float ga = g_alpha[gate], gl = g_lrg[gate], ge = g_eta[gate];
    float acc[2][4][4] = {};
    if (!segb) {
        const int n0 = (bid & 15) << 6, m0 = (bid >> 4) << 6;
        gemm_main<true, true>(d2h, d2l, a1h, a1l, m0, n0, D_, H_, R_,
                              sb, t, wm, wn, lane, acc);
        epi_store<4>(acc, m0, n0, H_, wm, wn, lane, nullptr, E2h, E2l, W2, M2, Wd2,
                     ga, gl, ge);
    } else {
        const int r = bid - 128;
        const int n0 = (r & 7) << 6, m0 = (r >> 3) << 6;
        gemm_main<true, true>(d1h, d1l, kchp, kclp, m0, n0, H_, D_, R_,
                              sb, t, wm, wn, lane, acc);
        epi_store<4>(acc, m0, n0, D_, wm, wn, lane, nullptr, E1h, E1l, W1, M1, Wd1,
                     ga, gl, ge);
    }
}

template <int EPI, bool AT, bool BT>
static void run(const bf16* Ah, const bf16* Al, const bf16* Bh, const bf16* Bl,
                float* C, bf16* Ch, bf16* Cl,
                const float* X1, float* U1, float* U2, int M, int N, int K, int gate)
{
    cudaFuncSetAttribute(mma_gemm<EPI, AT, BT>,
                         cudaFuncAttributeMaxDynamicSharedMemorySize, GSMEM);
    dim3 grid(N >> 6, M >> 6);
    mma_gemm<EPI, AT, BT><<<grid, 128, GSMEM>>>(Ah, Al, Bh, Bl, C, Ch, Cl, X1, U1, U2,
                                                M, N, K, gate);
}

// ---------------- misc kernels ----------------
__global__ void init_kernel(const float* __restrict__ W1, const float* __restrict__ W2)
{
    const size_t i = ((size_t)blockIdx.x * blockDim.x + threadIdx.x) * 2;
    if (i >= (size_t)H_ * D_) return;
    *(float2*)(g_Wd1 + i) = make_float2(0.f, 0.f);
    *(float2*)(g_M1  + i) = make_float2(0.f, 0.f);
    *(float2*)(g_Wd2 + i) = make_float2(0.f, 0.f);
    *(float2*)(g_M2  + i) = make_float2(0.f, 0.f);
    const float2 w1 = *(const float2*)(W1 + i);
    const float2 w2 = *(const float2*)(W2 + i);
    wr_hl(g_E1h, g_E1l, i, w1.x, w1.y);
    wr_hl(g_E2h, g_E2l, i, w2.x, w2.y);
}

__global__ void cvt_kernel(const float* __restrict__ s, bf16* __restrict__ h,
                           bf16* __restrict__ l, int n2)
{
    const int i = blockIdx.x * blockDim.x + threadIdx.x;
    if (i >= n2) return;
    const float2 v = ((const float2*)s)[i];
    wr_hl(h, l, (size_t)i * 2, v.x, v.y);
}

__global__ void conv_chunk_kernel(const float* __restrict__ in, const float* __restrict__ w,
                                  const float* __restrict__ bias,
                                  bf16* __restrict__ oh, bf16* __restrict__ ol,
                                  float* __restrict__ of)
{
    const size_t i = (size_t)blockIdx.x * blockDim.x + threadIdx.x;
    if (i >= (size_t)BS_ * D_) return;
    const int d = (int)(i & (D_ - 1));
    const size_t bs = i >> 9;
    const int s = (int)(bs & (S_ - 1));
    const int b = (int)(bs >> 12);
    float acc = bias[d];
#pragma unroll
    for (int j = 0; j < Kc_; j++) {
        const int sp = s - (Kc_ - 1) + j;
        if (sp >= 0)
            acc = fmaf(w[d * Kc_ + j], in[((size_t)b * S_ + sp) * D_ + d], acc);
    }
    const int c  = s >> 6;
    const int cs = s & 63;
    const size_t o = (((size_t)c * R_ + (b * CS_ + cs)) << 9) + d;
    if (of) {
        of[o] = acc;
    } else {
        const bf16 hv = __float2bfloat16_rn(acc);
        oh[o] = hv;
        ol[o] = __float2bfloat16_rn(acc - __bfloat162float(hv));
    }
}

__global__ void gates_kernel(const float* __restrict__ x,
                             const float* __restrict__ wd, const float* __restrict__ bd,
                             const float* __restrict__ wl, const float* __restrict__ bl,
                             const float* __restrict__ we, const float* __restrict__ be)
{
    const int c = blockIdx.x;
    const int t = threadIdx.x;
    const int b  = t >> 6;
    const int cs = t & 63;
    const float4* xr = (const float4*)(x + (((size_t)b * S_ + (size_t)c * CS_ + cs) << 9));
    const float4* w0 = (const float4*)wd;
    const float4* w1 = (const float4*)wl;
    const float4* w2 = (const float4*)we;
    float s0 = 0.f, s1 = 0.f, s2 = 0.f;
#pragma unroll 4
    for (int d = 0; d < D_ / 4; d++) {
        const float4 xv = xr[d];
        const float4 a0 = w0[d], a1 = w1[d], a2 = w2[d];
        s0 += xv.x * a0.x + xv.y * a0.y + xv.z * a0.z + xv.w * a0.w;
        s1 += xv.x * a1.x + xv.y * a1.y + xv.z * a1.z + xv.w * a1.w;
        s2 += xv.x * a2.x + xv.y * a2.y + xv.z * a2.z + xv.w * a2.w;
    }
    s0 = sigm(s0 + bd[0]);
    s1 = sigm(s1 + bl[0]);
    s2 = sigm(s2 + be[0]);

    __shared__ float r0[512], r1[512], r2[512];
    r0[t] = s0; r1[t] = s1; r2[t] = s2;
    __syncthreads();
    for (int off = 256; off > 0; off >>= 1) {
        if (t < off) { r0[t] += r0[t + off]; r1[t] += r1[t + off]; r2[t] += r2[t + off]; }
        __syncthreads();
    }
    if (t == 0) {
        g_alpha[c] = r0[0] * (1.0f / 512.0f);
        g_lrg[c]   = r1[0] * (1.0f / 512.0f);
        g_eta[c]   = r2[0] * (1.0f / 512.0f);
    }
}

__global__ void permute_y_kernel()
{
    const size_t i = (size_t)blockIdx.x * blockDim.x + threadIdx.x;
    if (i >= (size_t)BS_ * D_) return;
    const int d = (int)(i & (D_ - 1));
    const size_t rw = i >> 9;
    const int s = (int)(rw & (S_ - 1));
    const int b = (int)(rw >> 12);
    const int c  = s >> 6;
    const int cs = s & 63;
    const float v = g_ych[(((size_t)c * R_ + (b * CS_ + cs)) << 9) + d];
    const bf16 hv = __float2bfloat16_rn(v);
    g_yfh[i] = hv;
    g_yfl[i] = __float2bfloat16_rn(v - __bfloat162float(hv));
}

// ---------------- entry point ----------------
extern "C" void kernel_launch(void* const* d_in, const int* in_sizes, int n_in,
                              void* d_out, int out_size)
{
    (void)in_sizes; (void)n_in; (void)out_size;
    const float* x    = (const float*)d_in[0];
    const float* Wk   = (const float*)d_in[1];
    const float* Wv   = (const float*)d_in[2];
    const float* Wq   = (const float*)d_in[3];
    const float* Wout = (const float*)d_in[4];
    const float* ckw  = (const float*)d_in[5];
    const float* ckb  = (const float*)d_in[6];
    const float* cvw  = (const float*)d_in[7];
    const float* cvb  = (const float*)d_in[8];
    const float* cqw  = (const float*)d_in[9];
    const float* cqb  = (const float*)d_in[10];
    const float* wdec = (const float*)d_in[11];
    const float* bdec = (const float*)d_in[12];
    const float* wlr  = (const float*)d_in[13];
    const float* blr  = (const float*)d_in[14];
    const float* weta = (const float*)d_in[15];
    const float* beta = (const float*)d_in[16];
    const float* W1   = (const float*)d_in[17];
    const float* W2   = (const float*)d_in[18];
    float* out = (float*)d_out;

    float *proj, *vc, *ych, *sd, *Wd1, *M1, *Wd2, *M2;
    bf16 *xh, *xl, *kch, *kcl, *qch, *qcl, *yfh, *yfl;
    bf16 *a1h, *a1l, *d2h, *d2l, *d1h, *d1l, *tbh, *tbl;
    bf16 *E1h, *E1l, *E2h, *E2l, *Wkh, *Wkl, *Wvh, *Wvl, *Wqh, *Wql, *Woh, *Wol;
    cudaGetSymbolAddress((void**)&proj, g_proj);
    cudaGetSymbolAddress((void**)&vc,   g_vc);
    cudaGetSymbolAddress((void**)&ych,  g_ych);
    cudaGetSymbolAddress((void**)&sd,   g_sd);
    cudaGetSymbolAddress((void**)&Wd1,  g_Wd1);
    cudaGetSymbolAddress((void**)&M1,   g_M1);
    cudaGetSymbolAddress((void**)&Wd2,  g_Wd2);
    cudaGetSymbolAddress((void**)&M2,   g_M2);
    cudaGetSymbolAddress((void**)&xh,  g_xh);  cudaGetSymbolAddress((void**)&xl,  g_xl);
    cudaGetSymbolAddress((void**)&kch, g_kch); cudaGetSymbolAddress((void**)&kcl, g_kcl);
    cudaGetSymbolAddress((void**)&qch, g_qch); cudaGetSymbolAddress((void**)&qcl, g_qcl);
    cudaGetSymbolAddress((void**)&yfh, g_yfh); cudaGetSymbolAddress((void**)&yfl, g_yfl);
    cudaGetSymbolAddress((void**)&a1h, g_a1h); cudaGetSymbolAddress((void**)&a1l, g_a1l);
    cudaGetSymbolAddress((void**)&d2h, g_d2h); cudaGetSymbolAddress((void**)&d2l, g_d2l);
    cudaGetSymbolAddress((void**)&d1h, g_d1h); cudaGetSymbolAddress((void**)&d1l, g_d1l);
    cudaGetSymbolAddress((void**)&tbh, g_tbh); cudaGetSymbolAddress((void**)&tbl, g_tbl);
    cudaGetSymbolAddress((void**)&E1h, g_E1h); cudaGetSymbolAddress((void**)&E1l, g_E1l);
    cudaGetSymbolAddress((void**)&E2h, g_E2h); cudaGetSymbolAddress((void**)&E2l, g_E2l);
    cudaGetSymbolAddress((void**)&Wkh, g_Wkh); cudaGetSymbolAddress((void**)&Wkl, g_Wkl);
    cudaGetSymbolAddress((void**)&Wvh, g_Wvh); cudaGetSymbolAddress((void**)&Wvl, g_Wvl);
    cudaGetSymbolAddress((void**)&Wqh, g_Wqh); cudaGetSymbolAddress((void**)&Wql, g_Wql);
    cudaGetSymbolAddress((void**)&Woh, g_Woh); cudaGetSymbolAddress((void**)&Wol, g_Wol);

    const int nRD = R_ * D_;
    const int nHD = H_ * D_;
    const int nTOT = BS_ * D_;
    const int nDD = D_ * D_;

    init_kernel<<<(nHD / 2 + 255) / 256, 256>>>(W1, W2);
    gates_kernel<<<NC_, 512>>>(x, wdec, bdec, wlr, blr, weta, beta);

    cvt_kernel<<<(nTOT / 2 + 255) / 256, 256>>>(x, xh, xl, nTOT / 2);
    cvt_kernel<<<(nDD / 2 + 255) / 256, 256>>>(Wk, Wkh, Wkl, nDD / 2);
    cvt_kernel<<<(nDD / 2 + 255) / 256, 256>>>(Wv, Wvh, Wvl, nDD / 2);
    cvt_kernel<<<(nDD / 2 + 255) / 256, 256>>>(Wq, Wqh, Wql, nDD / 2);
    cvt_kernel<<<(nDD / 2 + 255) / 256, 256>>>(Wout, Woh, Wol, nDD / 2);

    run<0, false, false>(xh, xl, Wkh, Wkl, proj, nullptr, nullptr, nullptr, nullptr, nullptr,
                         BS_, D_, D_, 0);
    conv_chunk_kernel<<<(nTOT + 255) / 256, 256>>>(proj, ckw, ckb, kch, kcl, nullptr);
    run<0, false, false>(xh, xl, Wvh, Wvl, proj, nullptr, nullptr, nullptr, nullptr, nullptr,
                         BS_, D_, D_, 0);
    conv_chunk_kernel<<<(nTOT + 255) / 256, 256>>>(proj, cvw, cvb, nullptr, nullptr, vc);
    run<0, false, false>(xh, xl, Wqh, Wql, proj, nullptr, nullptr, nullptr, nullptr, nullptr,
                         BS_, D_, D_, 0);
    conv_chunk_kernel<<<(nTOT + 255) / 256, 256>>>(proj, cqw, cqb, qch, qcl, nullptr);

    cudaFuncSetAttribute(mma_gemm_dual<5, 1>,
                         cudaFuncAttributeMaxDynamicSharedMemorySize, GSMEM);
    cudaFuncSetAttribute(mma_gemm_dual<0, 2>,
                         cudaFuncAttributeMaxDynamicSharedMemorySize, GSMEM);
    cudaFuncSetAttribute(mma_update_dual,
                         cudaFuncAttributeMaxDynamicSharedMemorySize, GSMEM);

    // prologue: a1(0) + sd(0), d2(0)
    run<1, false, false>(kch, kcl, E1h, E1l, nullptr, a1h, a1l,
                         nullptr, sd, nullptr, R_, H_, D_, 0);
    run<2, false, false>(a1h, a1l, E2h, E2l, nullptr, d2h, d2l,
                         vc, nullptr, nullptr, R_, D_, H_, 0);

    for (int c = 0; c < NC_; c++) {
        const size_t off  = (size_t)c * nRD;
        const size_t offn = (size_t)(c + 1) * nRD;

        // d1(c) = (d2 E2_old) * sd
        run<3, false, true>(d2h, d2l, E2h, E2l, nullptr, d1h, d1l,
                            sd, nullptr, nullptr, R_, H_, D_, 0);
        // fused updates: g2 -> E2 new ; g1 -> E1 new
        mma_update_dual<<<256, 128, GSMEM>>>(d2h, d2l, a1h, a1l, d1h, d1l,
                                             kch + off, kcl + off,
                                             W2, M2, Wd2, E2h, E2l,
                                             W1, M1, Wd1, E1h, E1l, c);
        if (c + 1 < NC_) {
            // fused: tb(c) = silu(Qc(c) E1^T)  +  a1(c+1),sd(c+1) = f(Kc(c+1) E1^T)
            mma_gemm_dual<5, 1><<<dim3(H_ >> 6, 16), 128, GSMEM>>>(
                qch + off, qcl + off, kch + offn, kcl + offn, R_,
                E1h, E1l,
                nullptr, tbh, tbl, nullptr, nullptr,
                nullptr, a1h, a1l, nullptr, sd,
                H_, D_);
            // fused: y(c) = tb E2^T  +  d2(c+1) = clip(a1(c+1) E2^T - v(c+1))
            mma_gemm_dual<0, 2><<<dim3(D_ >> 6, 16), 128, GSMEM>>>(
                tbh, tbl, a1h, a1l, R_,
                E2h, E2l,
                ych + off, nullptr, nullptr, nullptr, nullptr,
                nullptr, d2h, d2l, vc + offn, nullptr,
                D_, H_);
        } else {
            run<5, false, false>(qch + off, qcl + off, E1h, E1l, nullptr, tbh, tbl,
                                 nullptr, nullptr, nullptr, R_, H_, D_, 0);
            run<0, false, false>(tbh, tbl, E2h, E2l, ych + off, nullptr, nullptr,
                                 nullptr, nullptr, nullptr, R_, D_, H_, 0);
        }
    }

    permute_y_kernel<<<(nTOT + 255) / 256, 256>>>();
    run<0, false, false>(yfh, yfl, Woh, Wol, out, nullptr, nullptr, nullptr, nullptr, nullptr,
                         BS_, D_, D_, 0);
}